// round 9
// baseline (speedup 1.0000x reference)
#include <cuda_runtime.h>
#include <math.h>

#define NCH    64
#define PITCH  65
#define NBATCH 4096
#define SPD    2080
#define EPSV   1e-6f
#define BN_SC  0.9999950000375f

__device__ float g_rm[NCH * NCH];
__device__ float g_rp[NCH * NCH];
__device__ float g_vec [(size_t)NBATCH * SPD];
__device__ float g_mu  [(size_t)NBATCH * 32];
__device__ float g_lv  [(size_t)NBATCH * 32];
__device__ float g_vdec[(size_t)NBATCH * SPD];

__device__ __forceinline__ void iu_decode(int u, int& i, int& j)
{
    int lo = 0, hi = 63;
    while (lo < hi) {
        int mid = (lo + hi + 1) >> 1;
        if (((mid * (129 - mid)) >> 1) <= u) lo = mid; else hi = mid - 1;
    }
    i = lo;
    j = lo + (u - ((lo * (129 - lo)) >> 1));
}

// in-block 64x64 GEMM, 256 threads, 4x4 tile each. AG/BG: operand in gmem
// (row-major stride 64) else smem (PITCH). BT: C = A*B^T. SC: scale A cols by ksc[k].
template<bool AG, bool BG, bool BT, bool SC>
__device__ __forceinline__ void bgemm(const float* __restrict__ Ao,
                                      const float* __restrict__ Bo,
                                      const float* __restrict__ ksc,
                                      float* __restrict__ C, int tid)
{
    const int i0 = (tid >> 4) * 4, j0 = (tid & 15) * 4;
    float acc[4][4];
#pragma unroll
    for (int r = 0; r < 4; r++)
#pragma unroll
        for (int c = 0; c < 4; c++) acc[r][c] = 0.f;
    for (int k = 0; k < 64; k++) {
        float a[4], b[4];
#pragma unroll
        for (int r = 0; r < 4; r++)
            a[r] = AG ? Ao[(i0 + r) * 64 + k] : Ao[(i0 + r) * PITCH + k];
        if (SC) {
            float f = ksc[k];
#pragma unroll
            for (int r = 0; r < 4; r++) a[r] *= f;
        }
#pragma unroll
        for (int c = 0; c < 4; c++) {
            if (BT) b[c] = BG ? Bo[(j0 + c) * 64 + k] : Bo[(j0 + c) * PITCH + k];
            else    b[c] = BG ? Bo[k * 64 + j0 + c]   : Bo[k * PITCH + j0 + c];
        }
#pragma unroll
        for (int r = 0; r < 4; r++)
#pragma unroll
            for (int c = 0; c < 4; c++) acc[r][c] += a[r] * b[c];
    }
#pragma unroll
    for (int r = 0; r < 4; r++)
#pragma unroll
        for (int c = 0; c < 4; c++)
            C[(i0 + r) * PITCH + j0 + c] = acc[r][c];
}

// parallel-order cyclic Jacobi, one 64x64 symmetric matrix per 256-thread block
template<bool WITHV>
__device__ void jacobi64(float* __restrict__ A, float* __restrict__ V, int sweeps,
                         int tid, float* sc, float* ss, int* sp, int* sq)
{
    for (int sw = 0; sw < sweeps; sw++)
        for (int r = 0; r < 63; r++) {
            if (tid < 32) {
                int p, q;
                if (tid == 0) { p = 63; q = r % 63; }
                else { p = (tid + r) % 63; q = (63 - tid + r) % 63; }
                float app = A[p * PITCH + p], aqq = A[q * PITCH + q];
                float apq = 0.5f * (A[p * PITCH + q] + A[q * PITCH + p]);
                float c = 1.f, s = 0.f;
                if (fabsf(apq) > 1e-36f) {
                    float tau = (aqq - app) / (2.f * apq);
                    float t = copysignf(1.f, tau) / (fabsf(tau) + sqrtf(1.f + tau * tau));
                    c = rsqrtf(1.f + t * t);
                    s = t * c;
                }
                sp[tid] = p; sq[tid] = q; sc[tid] = c; ss[tid] = s;
            }
            __syncthreads();
            for (int it = tid; it < 1024; it += 256) {
                int a = it >> 5, b = it & 31;
                int pa = sp[a], qa = sq[a], pb = sp[b], qb = sq[b];
                float ca = sc[a], sa = ss[a], cb = sc[b], sb = ss[b];
                float x00 = A[pa * PITCH + pb], x01 = A[pa * PITCH + qb];
                float x10 = A[qa * PITCH + pb], x11 = A[qa * PITCH + qb];
                float t00 = ca * x00 - sa * x10, t01 = ca * x01 - sa * x11;
                float t10 = sa * x00 + ca * x10, t11 = sa * x01 + ca * x11;
                A[pa * PITCH + pb] = cb * t00 - sb * t01;
                A[pa * PITCH + qb] = sb * t00 + cb * t01;
                A[qa * PITCH + pb] = cb * t10 - sb * t11;
                A[qa * PITCH + qb] = sb * t10 + cb * t11;
            }
            if (WITHV)
                for (int it = tid; it < 2048; it += 256) {
                    int a = it & 31, row = it >> 5;
                    int pa = sp[a], qa = sq[a];
                    float ca = sc[a], sa = ss[a];
                    float vp = V[row * PITCH + pa], vq = V[row * PITCH + qa];
                    V[row * PITCH + pa] = ca * vp - sa * vq;
                    V[row * PITCH + qa] = sa * vp + ca * vq;
                }
            __syncthreads();
        }
}

// dynamic smem: A, V, T = 3 * 64*65 floats = 49920 B (attribute set host-side)
__global__ void prep_ref_kernel(const float* __restrict__ ref,
                                float* __restrict__ rm_out, float* __restrict__ rp_out)
{
    extern __shared__ float smem[];
    float* A = smem;
    float* V = smem + 64 * PITCH;
    float* T = smem + 2 * 64 * PITCH;
    __shared__ float sc[32], ss[32]; __shared__ int sp[32], sq[32];
    __shared__ float w1[64], w2[64];
    int tid = threadIdx.x;
    for (int idx = tid; idx < 4096; idx += 256) {
        int i = idx >> 6, j = idx & 63;
        A[i * PITCH + j] = ref[idx] + ((i == j) ? EPSV : 0.f);
        V[i * PITCH + j] = (i == j) ? 1.f : 0.f;
    }
    __syncthreads();
    jacobi64<true>(A, V, 12, tid, sc, ss, sp, sq);
    if (tid < 64) {
        float w = fmaxf(A[tid * PITCH + tid], 1e-20f);
        w1[tid] = rsqrtf(w);
        w2[tid] = sqrtf(w);
    }
    __syncthreads();
    bgemm<false, false, true, true>(V, V, w1, T, tid);   // rm = V w^-1/2 V^T
    __syncthreads();
    for (int idx = tid; idx < 4096; idx += 256)
        rm_out[idx] = T[(idx >> 6) * PITCH + (idx & 63)];
    __syncthreads();
    bgemm<false, false, true, true>(V, V, w2, T, tid);   // rp = V w^1/2 V^T
    __syncthreads();
    for (int idx = tid; idx < 4096; idx += 256)
        rp_out[idx] = T[(idx >> 6) * PITCH + (idx & 63)];
}

__global__ void log_map_kernel(const float* __restrict__ x,
                               const float* __restrict__ rm, const float* __restrict__ rp,
                               float* __restrict__ vec_out)
{
    extern __shared__ float smem[];
    float* A = smem;
    float* V = smem + 64 * PITCH;
    float* T = smem + 2 * 64 * PITCH;
    __shared__ float sc[32], ss[32]; __shared__ int sp[32], sq[32];
    __shared__ float w[64];
    int tid = threadIdx.x;
    const float* X = x + (size_t)blockIdx.x * 4096;
    for (int idx = tid; idx < 4096; idx += 256) {
        int i = idx >> 6, j = idx & 63;
        T[i * PITCH + j] = X[idx];
        V[i * PITCH + j] = (i == j) ? 1.f : 0.f;
    }
    __syncthreads();
    bgemm<true, false, false, false>(rm, T, nullptr, A, tid);   // A = rm @ x
    __syncthreads();
    bgemm<false, true, false, false>(A, rm, nullptr, T, tid);   // T = s = rm x rm
    __syncthreads();
    jacobi64<true>(T, V, 8, tid, sc, ss, sp, sq);
    if (tid < 64) w[tid] = logf(fmaxf(T[tid * PITCH + tid], 1e-12f));
    __syncthreads();
    bgemm<false, false, true, true>(V, V, w, A, tid);           // A = log_s
    __syncthreads();
    bgemm<true, false, false, false>(rm, A, nullptr, T, tid);   // T = rm @ log_s
    __syncthreads();
    bgemm<false, true, false, false>(T, rp, nullptr, A, tid);   // A = tang
    __syncthreads();
    float* out = vec_out + (size_t)blockIdx.x * SPD;
    for (int u = tid; u < SPD; u += 256) {
        int i, j; iu_decode(u, i, j);
        out[u] = A[i * PITCH + j];
    }
}

__global__ void exp_map_kernel(const float* __restrict__ ref,
                               const float* __restrict__ vdec_in,
                               float* __restrict__ recon)
{
    extern __shared__ float smem[];
    float* A = smem;
    float* V = smem + 64 * PITCH;
    float* T = smem + 2 * 64 * PITCH;
    __shared__ float sc[32], ss[32]; __shared__ int sp[32], sq[32];
    __shared__ float w[64];
    __shared__ float sh_shift;
    int tid = threadIdx.x;
    const float* vd = vdec_in + (size_t)blockIdx.x * SPD;
    for (int u = tid; u < SPD; u += 256) {
        int i, j; iu_decode(u, i, j);
        float v = vd[u];
        if (i == j) A[i * PITCH + i] = v + EPSV;
        else { A[i * PITCH + j] = v; A[j * PITCH + i] = v; }
    }
    for (int idx = tid; idx < 4096; idx += 256) {
        int i = idx >> 6, j = idx & 63;
        V[i * PITCH + j] = (i == j) ? 1.f : 0.f;
    }
    __syncthreads();
    jacobi64<true>(A, V, 8, tid, sc, ss, sp, sq);
    if (tid < 64) w[tid] = expf(A[tid * PITCH + tid]);
    __syncthreads();
    bgemm<false, false, true, true>(V, V, w, T, tid);           // T = exp_a
    __syncthreads();
    bgemm<true, false, false, false>(ref, T, nullptr, A, tid);  // A = R = ref @ exp_a
    __syncthreads();
    for (int idx = tid; idx < 4096; idx += 256) {
        int i = idx >> 6, j = idx & 63;
        T[i * PITCH + j] = (i >= j) ? A[i * PITCH + j] : A[j * PITCH + i];
    }
    __syncthreads();
    jacobi64<false>(T, nullptr, 8, tid, sc, ss, sp, sq);
    if (tid == 0) {
        float m = T[0];
        for (int t = 1; t < 64; t++) m = fminf(m, T[t * PITCH + t]);
        sh_shift = fmaxf(EPSV - m, 0.f);
    }
    __syncthreads();
    float shf = sh_shift;
    float* out = recon + (size_t)blockIdx.x * 4096;
    for (int idx = tid; idx < 4096; idx += 256) {
        int i = idx >> 6, j = idx & 63;
        out[idx] = A[i * PITCH + j] + ((i == j) ? shf : 0.f);
    }
}

// ---------------- fused per-item MLP: one block per batch item, 128 threads ----------------
// Trivially-correct serial dot products; thread j owns neuron j of each layer.
__global__ void mlp_fused_kernel(
    const float* __restrict__ vec,
    const float* __restrict__ W1, const float* __restrict__ b1,
    const float* __restrict__ g1, const float* __restrict__ bb1,
    const float* __restrict__ W2, const float* __restrict__ b2,
    const float* __restrict__ g2, const float* __restrict__ bb2,
    const float* __restrict__ Wmu, const float* __restrict__ bmu,
    const float* __restrict__ Wlv, const float* __restrict__ blv,
    const float* __restrict__ D1, const float* __restrict__ db1,
    const float* __restrict__ dg1, const float* __restrict__ dbb1,
    const float* __restrict__ D2, const float* __restrict__ db2,
    const float* __restrict__ dg2, const float* __restrict__ dbb2,
    const float* __restrict__ D3, const float* __restrict__ db3,
    float* __restrict__ mu_out, float* __restrict__ lv_out,
    float* __restrict__ vdec_out)
{
    __shared__ float sv[SPD];
    __shared__ float h1[128], h2[64], zz[32], d1[64], d2[128];
    const int tid = threadIdx.x;
    const size_t b = blockIdx.x;
    const float* v = vec + b * SPD;
    for (int u = tid; u < SPD; u += 128) sv[u] = v[u];
    __syncthreads();
    // enc layer 1: 128 neurons, K=2080
    {
        float acc = 0.f;
        const float* wr = W1 + (size_t)tid * SPD;
        for (int k = 0; k < SPD; k++) acc += sv[k] * wr[k];
        acc += b1[tid];
        acc = (acc >= 0.f) ? acc : 0.2f * acc;
        h1[tid] = acc * (g1[tid] * BN_SC) + bb1[tid];
    }
    __syncthreads();
    // enc layer 2: 64 neurons, K=128
    if (tid < 64) {
        float acc = 0.f;
        const float* wr = W2 + tid * 128;
        for (int k = 0; k < 128; k++) acc += h1[k] * wr[k];
        acc += b2[tid];
        acc = (acc >= 0.f) ? acc : 0.2f * acc;
        h2[tid] = acc * (g2[tid] * BN_SC) + bb2[tid];
    }
    __syncthreads();
    // mu / logvar: 32 neurons each, K=64
    if (tid < 32) {
        float am = 0.f, al = 0.f;
        const float* wm = Wmu + tid * 64;
        const float* wl = Wlv + tid * 64;
        for (int k = 0; k < 64; k++) { am += h2[k] * wm[k]; al += h2[k] * wl[k]; }
        am += bmu[tid]; al += blv[tid];
        zz[tid] = am;
        mu_out[b * 32 + tid] = am;
        lv_out[b * 32 + tid] = al;
    }
    __syncthreads();
    // dec layer 1: 64 neurons, K=32
    if (tid < 64) {
        float acc = 0.f;
        const float* wr = D1 + tid * 32;
        for (int k = 0; k < 32; k++) acc += zz[k] * wr[k];
        acc += db1[tid];
        acc = (acc >= 0.f) ? acc : 0.2f * acc;
        d1[tid] = acc * (dg1[tid] * BN_SC) + dbb1[tid];
    }
    __syncthreads();
    // dec layer 2: 128 neurons, K=64
    {
        float acc = 0.f;
        const float* wr = D2 + tid * 64;
        for (int k = 0; k < 64; k++) acc += d1[k] * wr[k];
        acc += db2[tid];
        acc = (acc >= 0.f) ? acc : 0.2f * acc;
        d2[tid] = acc * (dg2[tid] * BN_SC) + dbb2[tid];
    }
    __syncthreads();
    // dec layer 3: 2080 neurons, K=128
    for (int j = tid; j < SPD; j += 128) {
        float acc = 0.f;
        const float* wr = D3 + (size_t)j * 128;
        for (int k = 0; k < 128; k++) acc += d2[k] * wr[k];
        vdec_out[b * SPD + j] = acc + db3[j];
    }
}

extern "C" void kernel_launch(void* const* d_in, const int* in_sizes, int n_in,
                              void* d_out, int out_size)
{
    const float* x      = (const float*)d_in[0];
    const float* ref    = (const float*)d_in[1];
    const float* enc_w1 = (const float*)d_in[2];
    const float* enc_b1 = (const float*)d_in[3];
    const float* bn1_g  = (const float*)d_in[4];
    const float* bn1_b  = (const float*)d_in[5];
    const float* enc_w2 = (const float*)d_in[6];
    const float* enc_b2 = (const float*)d_in[7];
    const float* bn2_g  = (const float*)d_in[8];
    const float* bn2_b  = (const float*)d_in[9];
    const float* mu_w   = (const float*)d_in[10];
    const float* mu_b   = (const float*)d_in[11];
    const float* lv_w   = (const float*)d_in[12];
    const float* lv_b   = (const float*)d_in[13];
    const float* dec_w1 = (const float*)d_in[14];
    const float* dec_b1 = (const float*)d_in[15];
    const float* dbn1_g = (const float*)d_in[16];
    const float* dbn1_b = (const float*)d_in[17];
    const float* dec_w2 = (const float*)d_in[18];
    const float* dec_b2 = (const float*)d_in[19];
    const float* dbn2_g = (const float*)d_in[20];
    const float* dbn2_b = (const float*)d_in[21];
    const float* dec_w3 = (const float*)d_in[22];
    const float* dec_b3 = (const float*)d_in[23];

    float* out = (float*)d_out;

    float *p_rm, *p_rp, *p_vec, *p_mu, *p_lv, *p_vdec;
    cudaGetSymbolAddress((void**)&p_rm,   g_rm);
    cudaGetSymbolAddress((void**)&p_rp,   g_rp);
    cudaGetSymbolAddress((void**)&p_vec,  g_vec);
    cudaGetSymbolAddress((void**)&p_mu,   g_mu);
    cudaGetSymbolAddress((void**)&p_lv,   g_lv);
    cudaGetSymbolAddress((void**)&p_vdec, g_vdec);

    const int dyn = 3 * 64 * PITCH * sizeof(float);   // 49920 B — needs attribute
    cudaFuncSetAttribute(prep_ref_kernel, cudaFuncAttributeMaxDynamicSharedMemorySize, dyn);
    cudaFuncSetAttribute(log_map_kernel,  cudaFuncAttributeMaxDynamicSharedMemorySize, dyn);
    cudaFuncSetAttribute(exp_map_kernel,  cudaFuncAttributeMaxDynamicSharedMemorySize, dyn);

    // mu/lv go straight to the d_out tail only when out_size exactly matches the
    // 3-output element count; otherwise they stay in private scratch (no OOB possible).
    const long long need = (long long)NBATCH * 4096 + 2LL * NBATCH * 32;  // 17039360
    float* mu_dst = ((long long)out_size == need) ? out + (size_t)NBATCH * 4096 : p_mu;
    float* lv_dst = ((long long)out_size == need) ? out + (size_t)NBATCH * 4096 + (size_t)NBATCH * 32 : p_lv;

    prep_ref_kernel<<<1, 256, dyn>>>(ref, p_rm, p_rp);
    log_map_kernel<<<NBATCH, 256, dyn>>>(x, p_rm, p_rp, p_vec);

    mlp_fused_kernel<<<NBATCH, 128>>>(p_vec,
        enc_w1, enc_b1, bn1_g, bn1_b,
        enc_w2, enc_b2, bn2_g, bn2_b,
        mu_w, mu_b, lv_w, lv_b,
        dec_w1, dec_b1, dbn1_g, dbn1_b,
        dec_w2, dec_b2, dbn2_g, dbn2_b,
        dec_w3, dec_b3,
        mu_dst, lv_dst, p_vdec);

    exp_map_kernel<<<NBATCH, 256, dyn>>>(ref, p_vdec, out);
}

// round 11
// speedup vs baseline: 1.2124x; 1.2124x over previous
#include <cuda_runtime.h>
#include <math.h>

#define NCH    64
#define PITCH  65          // pitch for A/T scratch matrices (odd: conflict-free scattered access)
#define PV     66          // pitch for transposed eigenvector matrix (even: float2-aligned rows)
#define NBATCH 4096
#define SPD    2080
#define EPSV   1e-6f
#define BN_SC  0.9999950000375f

__device__ float g_rm[NCH * NCH];
__device__ float g_rp[NCH * NCH];
__device__ float g_vec [(size_t)NBATCH * SPD];
__device__ float g_mu  [(size_t)NBATCH * 32];
__device__ float g_lv  [(size_t)NBATCH * 32];
__device__ float g_vdec[(size_t)NBATCH * SPD];

__device__ __forceinline__ void iu_decode(int u, int& i, int& j)
{
    int lo = 0, hi = 63;
    while (lo < hi) {
        int mid = (lo + hi + 1) >> 1;
        if (((mid * (129 - mid)) >> 1) <= u) lo = mid; else hi = mid - 1;
    }
    i = lo;
    j = lo + (u - ((lo * (129 - lo)) >> 1));
}

// in-block 64x64 GEMM, 256 threads, 4x4 tile each.
// AP/BP: row pitches of A and B operands (64 for gmem row-major, PITCH/PV for smem).
// BT: C = A*B^T.  SC: scale A columns by ksc[k].  C written with pitch PITCH.
template<int AP, int BP, bool BT, bool SC>
__device__ __forceinline__ void bgemm(const float* __restrict__ Ao,
                                      const float* __restrict__ Bo,
                                      const float* __restrict__ ksc,
                                      float* __restrict__ C, int tid)
{
    const int i0 = (tid >> 4) * 4, j0 = (tid & 15) * 4;
    float acc[4][4];
#pragma unroll
    for (int r = 0; r < 4; r++)
#pragma unroll
        for (int c = 0; c < 4; c++) acc[r][c] = 0.f;
    for (int k = 0; k < 64; k++) {
        float a[4], b[4];
#pragma unroll
        for (int r = 0; r < 4; r++)
            a[r] = Ao[(i0 + r) * AP + k];
        if (SC) {
            float f = ksc[k];
#pragma unroll
            for (int r = 0; r < 4; r++) a[r] *= f;
        }
#pragma unroll
        for (int c = 0; c < 4; c++)
            b[c] = BT ? Bo[(j0 + c) * BP + k] : Bo[k * BP + j0 + c];
#pragma unroll
        for (int r = 0; r < 4; r++)
#pragma unroll
            for (int c = 0; c < 4; c++) acc[r][c] += a[r] * b[c];
    }
#pragma unroll
    for (int r = 0; r < 4; r++)
#pragma unroll
        for (int c = 0; c < 4; c++)
            C[(i0 + r) * PITCH + j0 + c] = acc[r][c];
}

// C = V diag(d) V^T given Vt (rows = eigenvectors, pitch PV):
// C[i][j] = sum_t Vt[t][i] * d[t] * Vt[t][j]
__device__ __forceinline__ void bgemm_vtv(const float* __restrict__ Vt,
                                          const float* __restrict__ d,
                                          float* __restrict__ C, int tid)
{
    const int i0 = (tid >> 4) * 4, j0 = (tid & 15) * 4;
    float acc[4][4];
#pragma unroll
    for (int r = 0; r < 4; r++)
#pragma unroll
        for (int c = 0; c < 4; c++) acc[r][c] = 0.f;
    for (int k = 0; k < 64; k++) {
        const float* row = Vt + k * PV;
        float dk = d[k];
        float a[4], b[4];
#pragma unroll
        for (int r = 0; r < 4; r++) a[r] = row[i0 + r] * dk;
#pragma unroll
        for (int c = 0; c < 4; c++) b[c] = row[j0 + c];
#pragma unroll
        for (int r = 0; r < 4; r++)
#pragma unroll
            for (int c = 0; c < 4; c++) acc[r][c] += a[r] * b[c];
    }
#pragma unroll
    for (int r = 0; r < 4; r++)
#pragma unroll
        for (int c = 0; c < 4; c++)
            C[(i0 + r) * PITCH + j0 + c] = acc[r][c];
}

// parallel-order cyclic Jacobi, one 64x64 symmetric matrix per 256-thread block.
// Eigenvectors accumulated TRANSPOSED in Vt (row t = eigenvector t), float2 updates.
template<bool WITHV>
__device__ void jacobi64(float* __restrict__ A, float* __restrict__ Vt, int sweeps,
                         int tid, float* sc, float* ss, int* sp, int* sq)
{
    for (int sw = 0; sw < sweeps; sw++)
        for (int r = 0; r < 63; r++) {
            if (tid < 32) {
                int p, q;
                if (tid == 0) { p = 63; q = r % 63; }
                else { p = (tid + r) % 63; q = (63 - tid + r) % 63; }
                float app = A[p * PITCH + p], aqq = A[q * PITCH + q];
                float apq = 0.5f * (A[p * PITCH + q] + A[q * PITCH + p]);
                float c = 1.f, s = 0.f;
                if (fabsf(apq) > 1e-36f) {
                    float tau = (aqq - app) / (2.f * apq);
                    float t = copysignf(1.f, tau) / (fabsf(tau) + sqrtf(1.f + tau * tau));
                    c = rsqrtf(1.f + t * t);
                    s = t * c;
                }
                sp[tid] = p; sq[tid] = q; sc[tid] = c; ss[tid] = s;
            }
            __syncthreads();
            for (int it = tid; it < 1024; it += 256) {
                int a = it >> 5, b = it & 31;
                int pa = sp[a], qa = sq[a], pb = sp[b], qb = sq[b];
                float ca = sc[a], sa = ss[a], cb = sc[b], sb = ss[b];
                float x00 = A[pa * PITCH + pb], x01 = A[pa * PITCH + qb];
                float x10 = A[qa * PITCH + pb], x11 = A[qa * PITCH + qb];
                float t00 = ca * x00 - sa * x10, t01 = ca * x01 - sa * x11;
                float t10 = sa * x00 + ca * x10, t11 = sa * x01 + ca * x11;
                A[pa * PITCH + pb] = cb * t00 - sb * t01;
                A[pa * PITCH + qb] = sb * t00 + cb * t01;
                A[qa * PITCH + pb] = cb * t10 - sb * t11;
                A[qa * PITCH + qb] = sb * t10 + cb * t11;
            }
            if (WITHV)
                for (int it = tid; it < 1024; it += 256) {
                    int a = it >> 5, ch = it & 31;
                    int pa = sp[a], qa = sq[a];
                    float ca = sc[a], sa = ss[a];
                    float2* Pp = reinterpret_cast<float2*>(Vt + pa * PV) + ch;
                    float2* Pq = reinterpret_cast<float2*>(Vt + qa * PV) + ch;
                    float2 vp = *Pp, vq = *Pq;
                    float2 np, nq;
                    np.x = ca * vp.x - sa * vq.x; np.y = ca * vp.y - sa * vq.y;
                    nq.x = sa * vp.x + ca * vq.x; nq.y = sa * vp.y + ca * vq.y;
                    *Pp = np; *Pq = nq;
                }
            __syncthreads();
        }
}

// dynamic smem layout: A[64*PITCH], Vt[64*PV], T[64*PITCH] = 50176 B
#define SMEM_A  0
#define SMEM_VT (64 * PITCH)
#define SMEM_T  (64 * PITCH + 64 * PV)
#define DYN_B   ((64 * PITCH + 64 * PV + 64 * PITCH) * (int)sizeof(float))

__global__ void prep_ref_kernel(const float* __restrict__ ref,
                                float* __restrict__ rm_out, float* __restrict__ rp_out)
{
    extern __shared__ float smem[];
    float* A  = smem + SMEM_A;
    float* Vt = smem + SMEM_VT;
    float* T  = smem + SMEM_T;
    __shared__ float sc[32], ss[32]; __shared__ int sp[32], sq[32];
    __shared__ float w1[64], w2[64];
    int tid = threadIdx.x;
    for (int idx = tid; idx < 4096; idx += 256) {
        int i = idx >> 6, j = idx & 63;
        A[i * PITCH + j] = ref[idx] + ((i == j) ? EPSV : 0.f);
        Vt[i * PV + j]   = (i == j) ? 1.f : 0.f;
    }
    __syncthreads();
    jacobi64<true>(A, Vt, 12, tid, sc, ss, sp, sq);
    if (tid < 64) {
        float w = fmaxf(A[tid * PITCH + tid], 1e-20f);
        w1[tid] = rsqrtf(w);
        w2[tid] = sqrtf(w);
    }
    __syncthreads();
    bgemm_vtv(Vt, w1, T, tid);   // rm = V w^-1/2 V^T
    __syncthreads();
    for (int idx = tid; idx < 4096; idx += 256)
        rm_out[idx] = T[(idx >> 6) * PITCH + (idx & 63)];
    __syncthreads();
    bgemm_vtv(Vt, w2, T, tid);   // rp = V w^1/2 V^T
    __syncthreads();
    for (int idx = tid; idx < 4096; idx += 256)
        rp_out[idx] = T[(idx >> 6) * PITCH + (idx & 63)];
}

__global__ void log_map_kernel(const float* __restrict__ x,
                               const float* __restrict__ rm, const float* __restrict__ rp,
                               float* __restrict__ vec_out)
{
    extern __shared__ float smem[];
    float* A  = smem + SMEM_A;
    float* Vt = smem + SMEM_VT;
    float* T  = smem + SMEM_T;
    __shared__ float sc[32], ss[32]; __shared__ int sp[32], sq[32];
    __shared__ float w[64];
    int tid = threadIdx.x;
    const float* X = x + (size_t)blockIdx.x * 4096;
    for (int idx = tid; idx < 4096; idx += 256) {
        int i = idx >> 6, j = idx & 63;
        T[i * PITCH + j] = X[idx];
        Vt[i * PV + j]   = (i == j) ? 1.f : 0.f;
    }
    __syncthreads();
    bgemm<64, PITCH, false, false>(rm, T, nullptr, A, tid);   // A = rm @ x
    __syncthreads();
    bgemm<PITCH, 64, false, false>(A, rm, nullptr, T, tid);   // T = s = rm x rm
    __syncthreads();
    jacobi64<true>(T, Vt, 6, tid, sc, ss, sp, sq);
    if (tid < 64) w[tid] = logf(fmaxf(T[tid * PITCH + tid], 1e-12f));
    __syncthreads();
    bgemm_vtv(Vt, w, A, tid);                                 // A = log_s
    __syncthreads();
    bgemm<64, PITCH, false, false>(rm, A, nullptr, T, tid);   // T = rm @ log_s
    __syncthreads();
    bgemm<PITCH, 64, false, false>(T, rp, nullptr, A, tid);   // A = tang
    __syncthreads();
    float* out = vec_out + (size_t)blockIdx.x * SPD;
    for (int u = tid; u < SPD; u += 256) {
        int i, j; iu_decode(u, i, j);
        out[u] = A[i * PITCH + j];
    }
}

__global__ void exp_map_kernel(const float* __restrict__ ref,
                               const float* __restrict__ vdec_in,
                               float* __restrict__ recon)
{
    extern __shared__ float smem[];
    float* A  = smem + SMEM_A;
    float* Vt = smem + SMEM_VT;
    float* T  = smem + SMEM_T;
    __shared__ float sc[32], ss[32]; __shared__ int sp[32], sq[32];
    __shared__ float w[64];
    __shared__ float sh_shift;
    int tid = threadIdx.x;
    const float* vd = vdec_in + (size_t)blockIdx.x * SPD;
    for (int u = tid; u < SPD; u += 256) {
        int i, j; iu_decode(u, i, j);
        float v = vd[u];
        if (i == j) A[i * PITCH + i] = v + EPSV;
        else { A[i * PITCH + j] = v; A[j * PITCH + i] = v; }
    }
    for (int idx = tid; idx < 4096; idx += 256) {
        int i = idx >> 6, j = idx & 63;
        Vt[i * PV + j] = (i == j) ? 1.f : 0.f;
    }
    __syncthreads();
    jacobi64<true>(A, Vt, 6, tid, sc, ss, sp, sq);
    if (tid < 64) w[tid] = expf(A[tid * PITCH + tid]);
    __syncthreads();
    bgemm<64, PV, true, false>(ref, Vt, nullptr, T, tid);     // T = U = ref @ V
    __syncthreads();
    bgemm<PITCH, PV, false, true>(T, Vt, w, A, tid);          // A = R = U diag(e^w) V^T
    __syncthreads();
    for (int idx = tid; idx < 4096; idx += 256) {
        int i = idx >> 6, j = idx & 63;
        T[i * PITCH + j] = (i >= j) ? A[i * PITCH + j] : A[j * PITCH + i];
    }
    __syncthreads();
    jacobi64<false>(T, nullptr, 6, tid, sc, ss, sp, sq);
    if (tid == 0) {
        float m = T[0];
        for (int t = 1; t < 64; t++) m = fminf(m, T[t * PITCH + t]);
        sh_shift = fmaxf(EPSV - m, 0.f);
    }
    __syncthreads();
    float shf = sh_shift;
    float* out = recon + (size_t)blockIdx.x * 4096;
    for (int idx = tid; idx < 4096; idx += 256) {
        int i = idx >> 6, j = idx & 63;
        out[idx] = A[i * PITCH + j] + ((i == j) ? shf : 0.f);
    }
}

// ---------------- fused per-item MLP: one block per batch item, 128 threads ----------------
__global__ void mlp_fused_kernel(
    const float* __restrict__ vec,
    const float* __restrict__ W1, const float* __restrict__ b1,
    const float* __restrict__ g1, const float* __restrict__ bb1,
    const float* __restrict__ W2, const float* __restrict__ b2,
    const float* __restrict__ g2, const float* __restrict__ bb2,
    const float* __restrict__ Wmu, const float* __restrict__ bmu,
    const float* __restrict__ Wlv, const float* __restrict__ blv,
    const float* __restrict__ D1, const float* __restrict__ db1,
    const float* __restrict__ dg1, const float* __restrict__ dbb1,
    const float* __restrict__ D2, const float* __restrict__ db2,
    const float* __restrict__ dg2, const float* __restrict__ dbb2,
    const float* __restrict__ D3, const float* __restrict__ db3,
    float* __restrict__ mu_out, float* __restrict__ lv_out,
    float* __restrict__ vdec_out)
{
    __shared__ float sv[SPD];
    __shared__ float h1[128], h2[64], zz[32], d1[64], d2[128];
    const int tid = threadIdx.x;
    const size_t b = blockIdx.x;
    const float* v = vec + b * SPD;
    for (int u = tid; u < SPD; u += 128) sv[u] = v[u];
    __syncthreads();
    // enc layer 1: 128 neurons, K=2080 (4-way unrolled accumulators)
    {
        float a0 = 0.f, a1 = 0.f, a2 = 0.f, a3 = 0.f;
        const float* wr = W1 + (size_t)tid * SPD;
        for (int k = 0; k < SPD; k += 4) {
            a0 += sv[k]     * wr[k];
            a1 += sv[k + 1] * wr[k + 1];
            a2 += sv[k + 2] * wr[k + 2];
            a3 += sv[k + 3] * wr[k + 3];
        }
        float acc = (a0 + a1) + (a2 + a3) + b1[tid];
        acc = (acc >= 0.f) ? acc : 0.2f * acc;
        h1[tid] = acc * (g1[tid] * BN_SC) + bb1[tid];
    }
    __syncthreads();
    // enc layer 2: 64 neurons, K=128
    if (tid < 64) {
        float a0 = 0.f, a1 = 0.f;
        const float* wr = W2 + tid * 128;
        for (int k = 0; k < 128; k += 2) { a0 += h1[k] * wr[k]; a1 += h1[k + 1] * wr[k + 1]; }
        float acc = a0 + a1 + b2[tid];
        acc = (acc >= 0.f) ? acc : 0.2f * acc;
        h2[tid] = acc * (g2[tid] * BN_SC) + bb2[tid];
    }
    __syncthreads();
    // mu / logvar: 32 neurons each, K=64
    if (tid < 32) {
        float am = 0.f, al = 0.f;
        const float* wm = Wmu + tid * 64;
        const float* wl = Wlv + tid * 64;
        for (int k = 0; k < 64; k++) { am += h2[k] * wm[k]; al += h2[k] * wl[k]; }
        am += bmu[tid]; al += blv[tid];
        zz[tid] = am;
        mu_out[b * 32 + tid] = am;
        lv_out[b * 32 + tid] = al;
    }
    __syncthreads();
    // dec layer 1: 64 neurons, K=32
    if (tid < 64) {
        float acc = 0.f;
        const float* wr = D1 + tid * 32;
        for (int k = 0; k < 32; k++) acc += zz[k] * wr[k];
        acc += db1[tid];
        acc = (acc >= 0.f) ? acc : 0.2f * acc;
        d1[tid] = acc * (dg1[tid] * BN_SC) + dbb1[tid];
    }
    __syncthreads();
    // dec layer 2: 128 neurons, K=64
    {
        float acc = 0.f;
        const float* wr = D2 + tid * 64;
        for (int k = 0; k < 64; k++) acc += d1[k] * wr[k];
        acc += db2[tid];
        acc = (acc >= 0.f) ? acc : 0.2f * acc;
        d2[tid] = acc * (dg2[tid] * BN_SC) + dbb2[tid];
    }
    __syncthreads();
    // dec layer 3: 2080 neurons, K=128 (4-way unrolled)
    for (int j = tid; j < SPD; j += 128) {
        float a0 = 0.f, a1 = 0.f, a2 = 0.f, a3 = 0.f;
        const float* wr = D3 + (size_t)j * 128;
        for (int k = 0; k < 128; k += 4) {
            a0 += d2[k]     * wr[k];
            a1 += d2[k + 1] * wr[k + 1];
            a2 += d2[k + 2] * wr[k + 2];
            a3 += d2[k + 3] * wr[k + 3];
        }
        vdec_out[b * SPD + j] = (a0 + a1) + (a2 + a3) + db3[j];
    }
}

extern "C" void kernel_launch(void* const* d_in, const int* in_sizes, int n_in,
                              void* d_out, int out_size)
{
    const float* x      = (const float*)d_in[0];
    const float* ref    = (const float*)d_in[1];
    const float* enc_w1 = (const float*)d_in[2];
    const float* enc_b1 = (const float*)d_in[3];
    const float* bn1_g  = (const float*)d_in[4];
    const float* bn1_b  = (const float*)d_in[5];
    const float* enc_w2 = (const float*)d_in[6];
    const float* enc_b2 = (const float*)d_in[7];
    const float* bn2_g  = (const float*)d_in[8];
    const float* bn2_b  = (const float*)d_in[9];
    const float* mu_w   = (const float*)d_in[10];
    const float* mu_b   = (const float*)d_in[11];
    const float* lv_w   = (const float*)d_in[12];
    const float* lv_b   = (const float*)d_in[13];
    const float* dec_w1 = (const float*)d_in[14];
    const float* dec_b1 = (const float*)d_in[15];
    const float* dbn1_g = (const float*)d_in[16];
    const float* dbn1_b = (const float*)d_in[17];
    const float* dec_w2 = (const float*)d_in[18];
    const float* dec_b2 = (const float*)d_in[19];
    const float* dbn2_g = (const float*)d_in[20];
    const float* dbn2_b = (const float*)d_in[21];
    const float* dec_w3 = (const float*)d_in[22];
    const float* dec_b3 = (const float*)d_in[23];

    float* out = (float*)d_out;

    float *p_rm, *p_rp, *p_vec, *p_mu, *p_lv, *p_vdec;
    cudaGetSymbolAddress((void**)&p_rm,   g_rm);
    cudaGetSymbolAddress((void**)&p_rp,   g_rp);
    cudaGetSymbolAddress((void**)&p_vec,  g_vec);
    cudaGetSymbolAddress((void**)&p_mu,   g_mu);
    cudaGetSymbolAddress((void**)&p_lv,   g_lv);
    cudaGetSymbolAddress((void**)&p_vdec, g_vdec);

    cudaFuncSetAttribute(prep_ref_kernel, cudaFuncAttributeMaxDynamicSharedMemorySize, DYN_B);
    cudaFuncSetAttribute(log_map_kernel,  cudaFuncAttributeMaxDynamicSharedMemorySize, DYN_B);
    cudaFuncSetAttribute(exp_map_kernel,  cudaFuncAttributeMaxDynamicSharedMemorySize, DYN_B);

    const long long need = (long long)NBATCH * 4096 + 2LL * NBATCH * 32;  // 17039360
    float* mu_dst = ((long long)out_size == need) ? out + (size_t)NBATCH * 4096 : p_mu;
    float* lv_dst = ((long long)out_size == need) ? out + (size_t)NBATCH * 4096 + (size_t)NBATCH * 32 : p_lv;

    prep_ref_kernel<<<1, 256, DYN_B>>>(ref, p_rm, p_rp);
    log_map_kernel<<<NBATCH, 256, DYN_B>>>(x, p_rm, p_rp, p_vec);

    mlp_fused_kernel<<<NBATCH, 128>>>(p_vec,
        enc_w1, enc_b1, bn1_g, bn1_b,
        enc_w2, enc_b2, bn2_g, bn2_b,
        mu_w, mu_b, lv_w, lv_b,
        dec_w1, dec_b1, dbn1_g, dbn1_b,
        dec_w2, dec_b2, dbn2_g, dbn2_b,
        dec_w3, dec_b3,
        mu_dst, lv_dst, p_vdec);

    exp_map_kernel<<<NBATCH, 256, DYN_B>>>(ref, p_vdec, out);
}

// round 12
// speedup vs baseline: 1.2449x; 1.0268x over previous
#include <cuda_runtime.h>
#include <math.h>

#define NCH    64
#define PITCH  68          // one pitch for everything: f4/f2 aligned, conflict-benign
#define NBATCH 4096
#define SPD    2080
#define EPSV   1e-6f
#define BN_SC  0.9999950000375f

__device__ float g_rm[NCH * NCH];
__device__ float g_rp[NCH * NCH];
__device__ float g_vec [(size_t)NBATCH * SPD];
__device__ float g_mu  [(size_t)NBATCH * 32];
__device__ float g_lv  [(size_t)NBATCH * 32];
__device__ float g_vdec[(size_t)NBATCH * SPD];

__device__ __forceinline__ void iu_decode(int u, int& i, int& j)
{
    int lo = 0, hi = 63;
    while (lo < hi) {
        int mid = (lo + hi + 1) >> 1;
        if (((mid * (129 - mid)) >> 1) <= u) lo = mid; else hi = mid - 1;
    }
    i = lo;
    j = lo + (u - ((lo * (129 - lo)) >> 1));
}

// ---------------- in-block 64x64 GEMM, float4 loads, 4x4 tile/thread ----------------
// AP/BP: row pitches (64 gmem row-major, PITCH smem). BT: C=A*B^T. SC: scale A cols by ksc[k].
template<int AP, int BP, bool BT, bool SC>
__device__ __forceinline__ void bgemm(const float* __restrict__ Ao,
                                      const float* __restrict__ Bo,
                                      const float* __restrict__ ksc,
                                      float* __restrict__ C, int tid)
{
    const int i0 = (tid >> 4) * 4, j0 = (tid & 15) * 4;
    float acc[4][4];
#pragma unroll
    for (int r = 0; r < 4; r++)
#pragma unroll
        for (int c = 0; c < 4; c++) acc[r][c] = 0.f;

    for (int k4 = 0; k4 < 64; k4 += 4) {
        float a[4][4], b[4][4], ks[4];
        if (SC) {
            float4 s4 = *(const float4*)(ksc + k4);
            ks[0] = s4.x; ks[1] = s4.y; ks[2] = s4.z; ks[3] = s4.w;
        }
#pragma unroll
        for (int r = 0; r < 4; r++) {
            float4 v = *(const float4*)(Ao + (i0 + r) * AP + k4);
            a[r][0] = v.x; a[r][1] = v.y; a[r][2] = v.z; a[r][3] = v.w;
            if (SC) { a[r][0] *= ks[0]; a[r][1] *= ks[1]; a[r][2] *= ks[2]; a[r][3] *= ks[3]; }
        }
        if (BT) {
#pragma unroll
            for (int c = 0; c < 4; c++) {
                float4 v = *(const float4*)(Bo + (j0 + c) * BP + k4);
                b[0][c] = v.x; b[1][c] = v.y; b[2][c] = v.z; b[3][c] = v.w;
            }
        } else {
#pragma unroll
            for (int kk = 0; kk < 4; kk++) {
                float4 v = *(const float4*)(Bo + (k4 + kk) * BP + j0);
                b[kk][0] = v.x; b[kk][1] = v.y; b[kk][2] = v.z; b[kk][3] = v.w;
            }
        }
#pragma unroll
        for (int kk = 0; kk < 4; kk++)
#pragma unroll
            for (int r = 0; r < 4; r++)
#pragma unroll
                for (int c = 0; c < 4; c++)
                    acc[r][c] += a[r][kk] * b[kk][c];
    }
#pragma unroll
    for (int r = 0; r < 4; r++) {
        float4 v = make_float4(acc[r][0], acc[r][1], acc[r][2], acc[r][3]);
        *(float4*)(C + (i0 + r) * PITCH + j0) = v;
    }
}

// C = V diag(d) V^T given Vt (rows = eigenvectors, pitch PITCH)
__device__ __forceinline__ void bgemm_vtv(const float* __restrict__ Vt,
                                          const float* __restrict__ d,
                                          float* __restrict__ C, int tid)
{
    const int i0 = (tid >> 4) * 4, j0 = (tid & 15) * 4;
    float acc[4][4];
#pragma unroll
    for (int r = 0; r < 4; r++)
#pragma unroll
        for (int c = 0; c < 4; c++) acc[r][c] = 0.f;
    for (int t = 0; t < 64; t++) {
        const float* row = Vt + t * PITCH;
        float dk = d[t];
        float4 av = *(const float4*)(row + i0);
        float4 bv = *(const float4*)(row + j0);
        float a[4] = { av.x * dk, av.y * dk, av.z * dk, av.w * dk };
        float b[4] = { bv.x, bv.y, bv.z, bv.w };
#pragma unroll
        for (int r = 0; r < 4; r++)
#pragma unroll
            for (int c = 0; c < 4; c++) acc[r][c] += a[r] * b[c];
    }
#pragma unroll
    for (int r = 0; r < 4; r++) {
        float4 v = make_float4(acc[r][0], acc[r][1], acc[r][2], acc[r][3]);
        *(float4*)(C + (i0 + r) * PITCH + j0) = v;
    }
}

// ---------------- one parallel-order Jacobi sweep (63 rounds) ----------------
// Every warp redundantly computes all 32 rotations (lane = pair slot);
// update distributes pair-a coefficients via shfl (pair-b = own lane's).
template<bool WITHV>
__device__ __forceinline__ void jacobi_sweep(float* __restrict__ A, float* __restrict__ Vt,
                                             int lane, int warp)
{
    for (int r = 0; r < 63; r++) {
        int p, q;
        if (lane == 0) { p = 63; q = r; }
        else {
            p = lane + r;      if (p >= 63) p -= 63;
            q = 63 - lane + r; if (q >= 63) q -= 63;
        }
        float app = A[p * PITCH + p], aqq = A[q * PITCH + q];
        float apq = 0.5f * (A[p * PITCH + q] + A[q * PITCH + p]);
        float c = 1.f, s = 0.f;
        if (fabsf(apq) > 1e-36f) {
            float tau = (aqq - app) / (2.f * apq);
            float t = copysignf(1.f, tau) / (fabsf(tau) + sqrtf(1.f + tau * tau));
            c = rsqrtf(1.f + t * t);
            s = t * c;
        }
        __syncthreads();
#pragma unroll
        for (int n = 0; n < 4; n++) {
            int a = warp + 8 * n;
            float ca = __shfl_sync(0xffffffffu, c, a);
            float sa = __shfl_sync(0xffffffffu, s, a);
            int   pa = __shfl_sync(0xffffffffu, p, a);
            int   qa = __shfl_sync(0xffffffffu, q, a);
            float x00 = A[pa * PITCH + p], x01 = A[pa * PITCH + q];
            float x10 = A[qa * PITCH + p], x11 = A[qa * PITCH + q];
            float t00 = ca * x00 - sa * x10, t01 = ca * x01 - sa * x11;
            float t10 = sa * x00 + ca * x10, t11 = sa * x01 + ca * x11;
            A[pa * PITCH + p] = c * t00 - s * t01;
            A[pa * PITCH + q] = s * t00 + c * t01;
            A[qa * PITCH + p] = c * t10 - s * t11;
            A[qa * PITCH + q] = s * t10 + c * t11;
            if (WITHV) {
                float2* Pp = reinterpret_cast<float2*>(Vt + pa * PITCH) + lane;
                float2* Pq = reinterpret_cast<float2*>(Vt + qa * PITCH) + lane;
                float2 vp = *Pp, vq = *Pq;
                float2 np, nq;
                np.x = ca * vp.x - sa * vq.x; np.y = ca * vp.y - sa * vq.y;
                nq.x = sa * vp.x + ca * vq.x; nq.y = sa * vp.y + ca * vq.y;
                *Pp = np; *Pq = nq;
            }
        }
        __syncthreads();
    }
}

template<bool WITHV>
__device__ void jacobi64(float* __restrict__ A, float* __restrict__ Vt, int sweeps,
                         int lane, int warp)
{
    for (int sw = 0; sw < sweeps; sw++)
        jacobi_sweep<WITHV>(A, Vt, lane, warp);
}

// dynamic smem: A, Vt, T = 3 * 64*68 floats = 52224 B
#define DYN_B (3 * 64 * PITCH * (int)sizeof(float))

__global__ void prep_ref_kernel(const float* __restrict__ ref,
                                float* __restrict__ rm_out, float* __restrict__ rp_out)
{
    extern __shared__ float smem[];
    float* A  = smem;
    float* Vt = smem + 64 * PITCH;
    float* T  = smem + 2 * 64 * PITCH;
    __shared__ float w1[64], w2[64];
    int tid = threadIdx.x, lane = tid & 31, warp = tid >> 5;
    for (int idx = tid; idx < 4096; idx += 256) {
        int i = idx >> 6, j = idx & 63;
        A[i * PITCH + j] = ref[idx] + ((i == j) ? EPSV : 0.f);
        Vt[i * PITCH + j] = (i == j) ? 1.f : 0.f;
    }
    __syncthreads();
    jacobi64<true>(A, Vt, 12, lane, warp);
    if (tid < 64) {
        float w = fmaxf(A[tid * PITCH + tid], 1e-20f);
        w1[tid] = rsqrtf(w);
        w2[tid] = sqrtf(w);
    }
    __syncthreads();
    bgemm_vtv(Vt, w1, T, tid);
    __syncthreads();
    for (int idx = tid; idx < 4096; idx += 256)
        rm_out[idx] = T[(idx >> 6) * PITCH + (idx & 63)];
    __syncthreads();
    bgemm_vtv(Vt, w2, T, tid);
    __syncthreads();
    for (int idx = tid; idx < 4096; idx += 256)
        rp_out[idx] = T[(idx >> 6) * PITCH + (idx & 63)];
}

__global__ void log_map_kernel(const float* __restrict__ x,
                               const float* __restrict__ rm, const float* __restrict__ rp,
                               float* __restrict__ vec_out)
{
    extern __shared__ float smem[];
    float* A  = smem;
    float* Vt = smem + 64 * PITCH;
    float* T  = smem + 2 * 64 * PITCH;
    __shared__ float w[64];
    int tid = threadIdx.x, lane = tid & 31, warp = tid >> 5;
    const float* X = x + (size_t)blockIdx.x * 4096;
    for (int idx = tid; idx < 1024; idx += 256) {
        int i = idx >> 4, j4 = (idx & 15) << 2;
        *(float4*)(T + i * PITCH + j4) = *(const float4*)(X + i * 64 + j4);
    }
    for (int idx = tid; idx < 4096; idx += 256) {
        int i = idx >> 6, j = idx & 63;
        Vt[i * PITCH + j] = (i == j) ? 1.f : 0.f;
    }
    __syncthreads();
    bgemm<64, PITCH, false, false>(rm, T, nullptr, A, tid);   // A = rm @ x
    __syncthreads();
    bgemm<PITCH, 64, false, false>(A, rm, nullptr, T, tid);   // T = s = rm x rm
    __syncthreads();
    jacobi64<true>(T, Vt, 7, lane, warp);
    if (tid < 64) w[tid] = logf(fmaxf(T[tid * PITCH + tid], 1e-12f));
    __syncthreads();
    bgemm_vtv(Vt, w, A, tid);                                 // A = log_s
    __syncthreads();
    bgemm<64, PITCH, false, false>(rm, A, nullptr, T, tid);   // T = rm @ log_s
    __syncthreads();
    bgemm<PITCH, 64, false, false>(T, rp, nullptr, A, tid);   // A = tang
    __syncthreads();
    float* out = vec_out + (size_t)blockIdx.x * SPD;
    for (int u = tid; u < SPD; u += 256) {
        int i, j; iu_decode(u, i, j);
        out[u] = A[i * PITCH + j];
    }
}

__global__ void exp_map_kernel(const float* __restrict__ ref,
                               const float* __restrict__ vdec_in,
                               float* __restrict__ recon)
{
    extern __shared__ float smem[];
    float* A  = smem;
    float* Vt = smem + 64 * PITCH;
    float* T  = smem + 2 * 64 * PITCH;
    __shared__ float w[64];
    __shared__ float red[64];
    __shared__ float sh_shift;
    __shared__ int s_done;
    int tid = threadIdx.x, lane = tid & 31, warp = tid >> 5;
    const float* vd = vdec_in + (size_t)blockIdx.x * SPD;
    for (int u = tid; u < SPD; u += 256) {
        int i, j; iu_decode(u, i, j);
        float v = vd[u];
        if (i == j) A[i * PITCH + i] = v + EPSV;
        else { A[i * PITCH + j] = v; A[j * PITCH + i] = v; }
    }
    for (int idx = tid; idx < 4096; idx += 256) {
        int i = idx >> 6, j = idx & 63;
        Vt[i * PITCH + j] = (i == j) ? 1.f : 0.f;
    }
    __syncthreads();
    jacobi64<true>(A, Vt, 8, lane, warp);
    if (tid < 64) w[tid] = expf(A[tid * PITCH + tid]);
    __syncthreads();
    bgemm<64, PITCH, true, false>(ref, Vt, nullptr, T, tid);   // T = U = ref @ V
    __syncthreads();
    bgemm<PITCH, PITCH, false, true>(T, Vt, w, A, tid);        // A = R = U diag(e^w) V^T
    __syncthreads();
    for (int idx = tid; idx < 4096; idx += 256) {
        int i = idx >> 6, j = idx & 63;
        T[i * PITCH + j] = (i >= j) ? A[i * PITCH + j] : A[j * PITCH + i];
    }
    __syncthreads();
    // adaptive values-only eigensolve: Gershgorin early-certify shift = 0
    float shf = 0.f;
    {
        int done = 0;
        for (int sw = 0; sw < 8 && !done; sw++) {
            jacobi_sweep<false>(T, nullptr, lane, warp);
            if (sw >= 2) {
                int row = tid >> 2, c0 = (tid & 3) << 4;
                float part = 0.f;
                for (int j = 0; j < 16; j++) {
                    int col = c0 + j;
                    float v = T[row * PITCH + col];
                    part += (col == row) ? 0.f : fabsf(v);
                }
                part += __shfl_down_sync(0xffffffffu, part, 2);
                part += __shfl_down_sync(0xffffffffu, part, 1);
                if ((tid & 3) == 0) red[row] = T[row * PITCH + row] - part;
                __syncthreads();
                if (tid == 0) {
                    float m = red[0];
                    for (int i = 1; i < 64; i++) m = fminf(m, red[i]);
                    s_done = (m > EPSV) ? 1 : 0;
                }
                __syncthreads();
                done = s_done;
                __syncthreads();
            }
        }
        if (!done) {
            if (tid == 0) {
                float m = T[0];
                for (int t = 1; t < 64; t++) m = fminf(m, T[t * PITCH + t]);
                sh_shift = fmaxf(EPSV - m, 0.f);
            }
            __syncthreads();
            shf = sh_shift;
        }
    }
    float* out = recon + (size_t)blockIdx.x * 4096;
    for (int idx = tid; idx < 1024; idx += 256) {
        int i = idx >> 4, j4 = (idx & 15) << 2;
        float4 v = *(const float4*)(A + i * PITCH + j4);
        if (i >= j4 && i < j4 + 4) ((float*)&v)[i - j4] += shf;
        *(float4*)(out + i * 64 + j4) = v;
    }
}

// ---------------- fused per-item MLP: one block per batch item, 128 threads ----------------
__global__ void mlp_fused_kernel(
    const float* __restrict__ vec,
    const float* __restrict__ W1, const float* __restrict__ b1,
    const float* __restrict__ g1, const float* __restrict__ bb1,
    const float* __restrict__ W2, const float* __restrict__ b2,
    const float* __restrict__ g2, const float* __restrict__ bb2,
    const float* __restrict__ Wmu, const float* __restrict__ bmu,
    const float* __restrict__ Wlv, const float* __restrict__ blv,
    const float* __restrict__ D1, const float* __restrict__ db1,
    const float* __restrict__ dg1, const float* __restrict__ dbb1,
    const float* __restrict__ D2, const float* __restrict__ db2,
    const float* __restrict__ dg2, const float* __restrict__ dbb2,
    const float* __restrict__ D3, const float* __restrict__ db3,
    float* __restrict__ mu_out, float* __restrict__ lv_out,
    float* __restrict__ vdec_out)
{
    __shared__ float sv[SPD];
    __shared__ float h1[128], h2[64], zz[32], d1[64], d2[128];
    const int tid = threadIdx.x;
    const size_t b = blockIdx.x;
    const float* v = vec + b * SPD;
    for (int u = tid; u < SPD; u += 128) sv[u] = v[u];
    __syncthreads();
    {
        float a0 = 0.f, a1 = 0.f, a2 = 0.f, a3 = 0.f;
        const float* wr = W1 + (size_t)tid * SPD;
        for (int k = 0; k < SPD; k += 4) {
            a0 += sv[k]     * wr[k];
            a1 += sv[k + 1] * wr[k + 1];
            a2 += sv[k + 2] * wr[k + 2];
            a3 += sv[k + 3] * wr[k + 3];
        }
        float acc = (a0 + a1) + (a2 + a3) + b1[tid];
        acc = (acc >= 0.f) ? acc : 0.2f * acc;
        h1[tid] = acc * (g1[tid] * BN_SC) + bb1[tid];
    }
    __syncthreads();
    if (tid < 64) {
        float a0 = 0.f, a1 = 0.f;
        const float* wr = W2 + tid * 128;
        for (int k = 0; k < 128; k += 2) { a0 += h1[k] * wr[k]; a1 += h1[k + 1] * wr[k + 1]; }
        float acc = a0 + a1 + b2[tid];
        acc = (acc >= 0.f) ? acc : 0.2f * acc;
        h2[tid] = acc * (g2[tid] * BN_SC) + bb2[tid];
    }
    __syncthreads();
    if (tid < 32) {
        float am = 0.f, al = 0.f;
        const float* wm = Wmu + tid * 64;
        const float* wl = Wlv + tid * 64;
        for (int k = 0; k < 64; k++) { am += h2[k] * wm[k]; al += h2[k] * wl[k]; }
        am += bmu[tid]; al += blv[tid];
        zz[tid] = am;
        mu_out[b * 32 + tid] = am;
        lv_out[b * 32 + tid] = al;
    }
    __syncthreads();
    if (tid < 64) {
        float acc = 0.f;
        const float* wr = D1 + tid * 32;
        for (int k = 0; k < 32; k++) acc += zz[k] * wr[k];
        acc += db1[tid];
        acc = (acc >= 0.f) ? acc : 0.2f * acc;
        d1[tid] = acc * (dg1[tid] * BN_SC) + dbb1[tid];
    }
    __syncthreads();
    {
        float acc = 0.f;
        const float* wr = D2 + tid * 64;
        for (int k = 0; k < 64; k++) acc += d1[k] * wr[k];
        acc += db2[tid];
        acc = (acc >= 0.f) ? acc : 0.2f * acc;
        d2[tid] = acc * (dg2[tid] * BN_SC) + dbb2[tid];
    }
    __syncthreads();
    for (int j = tid; j < SPD; j += 128) {
        float a0 = 0.f, a1 = 0.f, a2 = 0.f, a3 = 0.f;
        const float* wr = D3 + (size_t)j * 128;
        for (int k = 0; k < 128; k += 4) {
            a0 += d2[k]     * wr[k];
            a1 += d2[k + 1] * wr[k + 1];
            a2 += d2[k + 2] * wr[k + 2];
            a3 += d2[k + 3] * wr[k + 3];
        }
        vdec_out[b * SPD + j] = (a0 + a1) + (a2 + a3) + db3[j];
    }
}

extern "C" void kernel_launch(void* const* d_in, const int* in_sizes, int n_in,
                              void* d_out, int out_size)
{
    const float* x      = (const float*)d_in[0];
    const float* ref    = (const float*)d_in[1];
    const float* enc_w1 = (const float*)d_in[2];
    const float* enc_b1 = (const float*)d_in[3];
    const float* bn1_g  = (const float*)d_in[4];
    const float* bn1_b  = (const float*)d_in[5];
    const float* enc_w2 = (const float*)d_in[6];
    const float* enc_b2 = (const float*)d_in[7];
    const float* bn2_g  = (const float*)d_in[8];
    const float* bn2_b  = (const float*)d_in[9];
    const float* mu_w   = (const float*)d_in[10];
    const float* mu_b   = (const float*)d_in[11];
    const float* lv_w   = (const float*)d_in[12];
    const float* lv_b   = (const float*)d_in[13];
    const float* dec_w1 = (const float*)d_in[14];
    const float* dec_b1 = (const float*)d_in[15];
    const float* dbn1_g = (const float*)d_in[16];
    const float* dbn1_b = (const float*)d_in[17];
    const float* dec_w2 = (const float*)d_in[18];
    const float* dec_b2 = (const float*)d_in[19];
    const float* dbn2_g = (const float*)d_in[20];
    const float* dbn2_b = (const float*)d_in[21];
    const float* dec_w3 = (const float*)d_in[22];
    const float* dec_b3 = (const float*)d_in[23];

    float* out = (float*)d_out;

    float *p_rm, *p_rp, *p_vec, *p_mu, *p_lv, *p_vdec;
    cudaGetSymbolAddress((void**)&p_rm,   g_rm);
    cudaGetSymbolAddress((void**)&p_rp,   g_rp);
    cudaGetSymbolAddress((void**)&p_vec,  g_vec);
    cudaGetSymbolAddress((void**)&p_mu,   g_mu);
    cudaGetSymbolAddress((void**)&p_lv,   g_lv);
    cudaGetSymbolAddress((void**)&p_vdec, g_vdec);

    cudaFuncSetAttribute(prep_ref_kernel, cudaFuncAttributeMaxDynamicSharedMemorySize, DYN_B);
    cudaFuncSetAttribute(log_map_kernel,  cudaFuncAttributeMaxDynamicSharedMemorySize, DYN_B);
    cudaFuncSetAttribute(exp_map_kernel,  cudaFuncAttributeMaxDynamicSharedMemorySize, DYN_B);

    const long long need = (long long)NBATCH * 4096 + 2LL * NBATCH * 32;  // 17039360
    float* mu_dst = ((long long)out_size == need) ? out + (size_t)NBATCH * 4096 : p_mu;
    float* lv_dst = ((long long)out_size == need) ? out + (size_t)NBATCH * 4096 + (size_t)NBATCH * 32 : p_lv;

    prep_ref_kernel<<<1, 256, DYN_B>>>(ref, p_rm, p_rp);
    log_map_kernel<<<NBATCH, 256, DYN_B>>>(x, p_rm, p_rp, p_vec);

    mlp_fused_kernel<<<NBATCH, 128>>>(p_vec,
        enc_w1, enc_b1, bn1_g, bn1_b,
        enc_w2, enc_b2, bn2_g, bn2_b,
        mu_w, mu_b, lv_w, lv_b,
        dec_w1, dec_b1, dbn1_g, dbn1_b,
        dec_w2, dec_b2, dbn2_g, dbn2_b,
        dec_w3, dec_b3,
        mu_dst, lv_dst, p_vdec);

    exp_map_kernel<<<NBATCH, 256, DYN_B>>>(ref, p_vdec, out);
}

// round 13
// speedup vs baseline: 1.5834x; 1.2719x over previous
#include <cuda_runtime.h>
#include <math.h>

#define NCH    64
#define PITCH  68
#define NBATCH 4096
#define SPD    2080
#define EPSV   1e-6f
#define BN_SC  0.9999950000375f

__device__ float g_rm[NCH * NCH];
__device__ float g_rp[NCH * NCH];
__device__ float g_vec [(size_t)NBATCH * SPD];
__device__ float g_mu  [(size_t)NBATCH * 32];
__device__ float g_lv  [(size_t)NBATCH * 32];
__device__ float g_vdec[(size_t)NBATCH * SPD];

__device__ __forceinline__ void iu_decode(int u, int& i, int& j)
{
    int lo = 0, hi = 63;
    while (lo < hi) {
        int mid = (lo + hi + 1) >> 1;
        if (((mid * (129 - mid)) >> 1) <= u) lo = mid; else hi = mid - 1;
    }
    i = lo;
    j = lo + (u - ((lo * (129 - lo)) >> 1));
}

// ---------------- in-block 64x64 GEMM, 4x4 tile/thread, scalar loads (low-reg) --------
// Compute into registers, BARRIER, then write — so dst may alias either operand.
// AP/BP: row pitches (64 gmem row-major, PITCH smem). BT: C=A*B^T. SC: scale A cols.
template<int AP, int BP, bool BT, bool SC>
__device__ __forceinline__ void bgemm(const float* __restrict__ Ao,
                                      const float* __restrict__ Bo,
                                      const float* __restrict__ ksc,
                                      float* __restrict__ C, int tid)
{
    const int i0 = (tid >> 4) * 4, j0 = (tid & 15) * 4;
    float acc[4][4];
#pragma unroll
    for (int r = 0; r < 4; r++)
#pragma unroll
        for (int c = 0; c < 4; c++) acc[r][c] = 0.f;
    for (int k = 0; k < 64; k++) {
        float a[4], b[4];
#pragma unroll
        for (int r = 0; r < 4; r++) a[r] = Ao[(i0 + r) * AP + k];
        if (SC) {
            float f = ksc[k];
#pragma unroll
            for (int r = 0; r < 4; r++) a[r] *= f;
        }
#pragma unroll
        for (int c = 0; c < 4; c++)
            b[c] = BT ? Bo[(j0 + c) * BP + k] : Bo[k * BP + j0 + c];
#pragma unroll
        for (int r = 0; r < 4; r++)
#pragma unroll
            for (int c = 0; c < 4; c++) acc[r][c] += a[r] * b[c];
    }
    __syncthreads();   // all reads done before any writes (enables in-place)
#pragma unroll
    for (int r = 0; r < 4; r++)
#pragma unroll
        for (int c = 0; c < 4; c++)
            C[(i0 + r) * PITCH + j0 + c] = acc[r][c];
    __syncthreads();
}

// C = V diag(d) V^T given Vt (rows = eigenvectors, pitch PITCH); same write protocol.
__device__ __forceinline__ void bgemm_vtv(const float* __restrict__ Vt,
                                          const float* __restrict__ d,
                                          float* __restrict__ C, int tid)
{
    const int i0 = (tid >> 4) * 4, j0 = (tid & 15) * 4;
    float acc[4][4];
#pragma unroll
    for (int r = 0; r < 4; r++)
#pragma unroll
        for (int c = 0; c < 4; c++) acc[r][c] = 0.f;
    for (int t = 0; t < 64; t++) {
        const float* row = Vt + t * PITCH;
        float dk = d[t];
        float a[4], b[4];
#pragma unroll
        for (int r = 0; r < 4; r++) a[r] = row[i0 + r] * dk;
#pragma unroll
        for (int c = 0; c < 4; c++) b[c] = row[j0 + c];
#pragma unroll
        for (int r = 0; r < 4; r++)
#pragma unroll
            for (int c = 0; c < 4; c++) acc[r][c] += a[r] * b[c];
    }
    __syncthreads();
#pragma unroll
    for (int r = 0; r < 4; r++)
#pragma unroll
        for (int c = 0; c < 4; c++)
            C[(i0 + r) * PITCH + j0 + c] = acc[r][c];
    __syncthreads();
}

// ---------------- one parallel-order Jacobi sweep (63 rounds) ----------------
template<bool WITHV>
__device__ __forceinline__ void jacobi_sweep(float* __restrict__ A, float* __restrict__ Vt,
                                             int lane, int warp)
{
    for (int r = 0; r < 63; r++) {
        int p, q;
        if (lane == 0) { p = 63; q = r; }
        else {
            p = lane + r;      if (p >= 63) p -= 63;
            q = 63 - lane + r; if (q >= 63) q -= 63;
        }
        float app = A[p * PITCH + p], aqq = A[q * PITCH + q];
        float apq = 0.5f * (A[p * PITCH + q] + A[q * PITCH + p]);
        float c = 1.f, s = 0.f;
        if (fabsf(apq) > 1e-36f) {
            float tau = (aqq - app) / (2.f * apq);
            float t = copysignf(1.f, tau) / (fabsf(tau) + sqrtf(1.f + tau * tau));
            c = rsqrtf(1.f + t * t);
            s = t * c;
        }
        __syncthreads();
#pragma unroll
        for (int n = 0; n < 4; n++) {
            int a = warp + 8 * n;
            float ca = __shfl_sync(0xffffffffu, c, a);
            float sa = __shfl_sync(0xffffffffu, s, a);
            int   pa = __shfl_sync(0xffffffffu, p, a);
            int   qa = __shfl_sync(0xffffffffu, q, a);
            float x00 = A[pa * PITCH + p], x01 = A[pa * PITCH + q];
            float x10 = A[qa * PITCH + p], x11 = A[qa * PITCH + q];
            float t00 = ca * x00 - sa * x10, t01 = ca * x01 - sa * x11;
            float t10 = sa * x00 + ca * x10, t11 = sa * x01 + ca * x11;
            A[pa * PITCH + p] = c * t00 - s * t01;
            A[pa * PITCH + q] = s * t00 + c * t01;
            A[qa * PITCH + p] = c * t10 - s * t11;
            A[qa * PITCH + q] = s * t10 + c * t11;
            if (WITHV) {
                float2* Pp = reinterpret_cast<float2*>(Vt + pa * PITCH) + lane;
                float2* Pq = reinterpret_cast<float2*>(Vt + qa * PITCH) + lane;
                float2 vp = *Pp, vq = *Pq;
                float2 np, nq;
                np.x = ca * vp.x - sa * vq.x; np.y = ca * vp.y - sa * vq.y;
                nq.x = sa * vp.x + ca * vq.x; nq.y = sa * vp.y + ca * vq.y;
                *Pp = np; *Pq = nq;
            }
        }
        __syncthreads();
    }
}

template<bool WITHV>
__device__ void jacobi64(float* __restrict__ A, float* __restrict__ Vt, int sweeps,
                         int lane, int warp)
{
    for (int sw = 0; sw < sweeps; sw++)
        jacobi_sweep<WITHV>(A, Vt, lane, warp);
}

// dynamic smem: A, Vt = 2 * 64*68 floats = 34816 B  -> 6 blocks/SM
#define DYN_B (2 * 64 * PITCH * (int)sizeof(float))

__global__ __launch_bounds__(256, 6)
void prep_ref_kernel(const float* __restrict__ ref,
                     float* __restrict__ rm_out, float* __restrict__ rp_out)
{
    extern __shared__ float smem[];
    float* A  = smem;
    float* Vt = smem + 64 * PITCH;
    __shared__ float w1[64], w2[64];
    int tid = threadIdx.x, lane = tid & 31, warp = tid >> 5;
    for (int idx = tid; idx < 4096; idx += 256) {
        int i = idx >> 6, j = idx & 63;
        A[i * PITCH + j] = ref[idx] + ((i == j) ? EPSV : 0.f);
        Vt[i * PITCH + j] = (i == j) ? 1.f : 0.f;
    }
    __syncthreads();
    jacobi64<true>(A, Vt, 12, lane, warp);
    if (tid < 64) {
        float w = fmaxf(A[tid * PITCH + tid], 1e-20f);
        w1[tid] = rsqrtf(w);
        w2[tid] = sqrtf(w);
    }
    __syncthreads();
    bgemm_vtv(Vt, w1, A, tid);   // rm = V w^-1/2 V^T  (A dead)
    for (int idx = tid; idx < 4096; idx += 256)
        rm_out[idx] = A[(idx >> 6) * PITCH + (idx & 63)];
    __syncthreads();
    bgemm_vtv(Vt, w2, A, tid);   // rp = V w^1/2 V^T
    for (int idx = tid; idx < 4096; idx += 256)
        rp_out[idx] = A[(idx >> 6) * PITCH + (idx & 63)];
}

__global__ __launch_bounds__(256, 6)
void log_map_kernel(const float* __restrict__ x,
                    const float* __restrict__ rm, const float* __restrict__ rp,
                    float* __restrict__ vec_out)
{
    extern __shared__ float smem[];
    float* A  = smem;
    float* Vt = smem + 64 * PITCH;
    __shared__ float w[64];
    int tid = threadIdx.x, lane = tid & 31, warp = tid >> 5;
    const float* X = x + (size_t)blockIdx.x * 4096;
    for (int idx = tid; idx < 1024; idx += 256) {
        int i = idx >> 4, j4 = (idx & 15) << 2;
        *(float4*)(A + i * PITCH + j4) = *(const float4*)(X + i * 64 + j4);
    }
    __syncthreads();
    bgemm<64, PITCH, false, false>(rm, A, nullptr, Vt, tid);   // Vt = rm @ x
    bgemm<PITCH, 64, false, false>(Vt, rm, nullptr, A, tid);   // A = s = rm x rm
    // now init eigenvector accumulator (Vt consumed)
    for (int idx = tid; idx < 4096; idx += 256) {
        int i = idx >> 6, j = idx & 63;
        Vt[i * PITCH + j] = (i == j) ? 1.f : 0.f;
    }
    __syncthreads();
    jacobi64<true>(A, Vt, 7, lane, warp);
    if (tid < 64) w[tid] = logf(fmaxf(A[tid * PITCH + tid], 1e-12f));
    __syncthreads();
    bgemm_vtv(Vt, w, A, tid);                                  // A = log_s (in place over s)
    bgemm<64, PITCH, false, false>(rm, A, nullptr, A, tid);    // A = rm @ log_s (in-place)
    bgemm<PITCH, 64, false, false>(A, rp, nullptr, A, tid);    // A = tang     (in-place)
    float* out = vec_out + (size_t)blockIdx.x * SPD;
    for (int u = tid; u < SPD; u += 256) {
        int i, j; iu_decode(u, i, j);
        out[u] = A[i * PITCH + j];
    }
}

__global__ __launch_bounds__(256, 6)
void exp_map_kernel(const float* __restrict__ ref,
                    const float* __restrict__ vdec_in,
                    float* __restrict__ recon)
{
    extern __shared__ float smem[];
    float* A  = smem;
    float* Vt = smem + 64 * PITCH;
    __shared__ float w[64];
    __shared__ float red[64];
    __shared__ float sh_shift;
    __shared__ int s_done;
    int tid = threadIdx.x, lane = tid & 31, warp = tid >> 5;
    const float* vd = vdec_in + (size_t)blockIdx.x * SPD;
    for (int u = tid; u < SPD; u += 256) {
        int i, j; iu_decode(u, i, j);
        float v = vd[u];
        if (i == j) A[i * PITCH + i] = v + EPSV;
        else { A[i * PITCH + j] = v; A[j * PITCH + i] = v; }
    }
    for (int idx = tid; idx < 4096; idx += 256) {
        int i = idx >> 6, j = idx & 63;
        Vt[i * PITCH + j] = (i == j) ? 1.f : 0.f;
    }
    __syncthreads();
    jacobi64<true>(A, Vt, 8, lane, warp);
    if (tid < 64) w[tid] = expf(A[tid * PITCH + tid]);
    __syncthreads();
    bgemm<64, PITCH, true, false>(ref, Vt, nullptr, A, tid);    // A = U = ref @ V (A dead)
    bgemm<PITCH, PITCH, false, true>(A, Vt, w, A, tid);         // A = R = U diag(e^w) V^T
    // sym_lower(R) into Vt (Vt dead), then values-only eigensolve on Vt
    for (int idx = tid; idx < 4096; idx += 256) {
        int i = idx >> 6, j = idx & 63;
        Vt[i * PITCH + j] = (i >= j) ? A[i * PITCH + j] : A[j * PITCH + i];
    }
    __syncthreads();
    float shf = 0.f;
    {
        int done = 0;
        for (int sw = 0; sw < 8 && !done; sw++) {
            jacobi_sweep<false>(Vt, nullptr, lane, warp);
            if (sw >= 2) {
                int row = tid >> 2, c0 = (tid & 3) << 4;
                float part = 0.f;
                for (int j = 0; j < 16; j++) {
                    int col = c0 + j;
                    float v = Vt[row * PITCH + col];
                    part += (col == row) ? 0.f : fabsf(v);
                }
                part += __shfl_down_sync(0xffffffffu, part, 2);
                part += __shfl_down_sync(0xffffffffu, part, 1);
                if ((tid & 3) == 0) red[row] = Vt[row * PITCH + row] - part;
                __syncthreads();
                if (tid == 0) {
                    float m = red[0];
                    for (int i = 1; i < 64; i++) m = fminf(m, red[i]);
                    s_done = (m > EPSV) ? 1 : 0;
                }
                __syncthreads();
                done = s_done;
                __syncthreads();
            }
        }
        if (!done) {
            if (tid == 0) {
                float m = Vt[0];
                for (int t = 1; t < 64; t++) m = fminf(m, Vt[t * PITCH + t]);
                sh_shift = fmaxf(EPSV - m, 0.f);
            }
            __syncthreads();
            shf = sh_shift;
        }
    }
    float* out = recon + (size_t)blockIdx.x * 4096;
    for (int idx = tid; idx < 1024; idx += 256) {
        int i = idx >> 4, j4 = (idx & 15) << 2;
        float4 v = *(const float4*)(A + i * PITCH + j4);
        if (i >= j4 && i < j4 + 4) ((float*)&v)[i - j4] += shf;
        *(float4*)(out + i * 64 + j4) = v;
    }
}

// ---------------- fused MLP: 4 items per 128-thread block (W reuse) ----------------
__global__ void mlp_fused_kernel(
    const float* __restrict__ vec,
    const float* __restrict__ W1, const float* __restrict__ b1,
    const float* __restrict__ g1, const float* __restrict__ bb1,
    const float* __restrict__ W2, const float* __restrict__ b2,
    const float* __restrict__ g2, const float* __restrict__ bb2,
    const float* __restrict__ Wmu, const float* __restrict__ bmu,
    const float* __restrict__ Wlv, const float* __restrict__ blv,
    const float* __restrict__ D1, const float* __restrict__ db1,
    const float* __restrict__ dg1, const float* __restrict__ dbb1,
    const float* __restrict__ D2, const float* __restrict__ db2,
    const float* __restrict__ dg2, const float* __restrict__ dbb2,
    const float* __restrict__ D3, const float* __restrict__ db3,
    float* __restrict__ mu_out, float* __restrict__ lv_out,
    float* __restrict__ vdec_out)
{
    __shared__ float sv[4][SPD];
    __shared__ float h1[4][128], h2[4][64], zz[4][32], d1[4][64], d2[4][128];
    const int tid = threadIdx.x;
    const size_t b0 = (size_t)blockIdx.x * 4;
#pragma unroll
    for (int it = 0; it < 4; it++)
        for (int u = tid; u < SPD; u += 128) sv[it][u] = vec[(b0 + it) * SPD + u];
    __syncthreads();
    // enc1: neuron tid, K=2080, 4 items share the weight row
    {
        float a0 = 0.f, a1 = 0.f, a2 = 0.f, a3 = 0.f;
        const float* wr = W1 + (size_t)tid * SPD;
        for (int k = 0; k < SPD; k++) {
            float wv = wr[k];
            a0 += sv[0][k] * wv; a1 += sv[1][k] * wv;
            a2 += sv[2][k] * wv; a3 += sv[3][k] * wv;
        }
        float bs = b1[tid], scl = g1[tid] * BN_SC, sh = bb1[tid];
        float t;
        t = a0 + bs; t = (t >= 0.f) ? t : 0.2f * t; h1[0][tid] = t * scl + sh;
        t = a1 + bs; t = (t >= 0.f) ? t : 0.2f * t; h1[1][tid] = t * scl + sh;
        t = a2 + bs; t = (t >= 0.f) ? t : 0.2f * t; h1[2][tid] = t * scl + sh;
        t = a3 + bs; t = (t >= 0.f) ? t : 0.2f * t; h1[3][tid] = t * scl + sh;
    }
    __syncthreads();
    if (tid < 64) {
        float a0 = 0.f, a1 = 0.f, a2 = 0.f, a3 = 0.f;
        const float* wr = W2 + tid * 128;
        for (int k = 0; k < 128; k++) {
            float wv = wr[k];
            a0 += h1[0][k] * wv; a1 += h1[1][k] * wv;
            a2 += h1[2][k] * wv; a3 += h1[3][k] * wv;
        }
        float bs = b2[tid], scl = g2[tid] * BN_SC, sh = bb2[tid];
        float t;
        t = a0 + bs; t = (t >= 0.f) ? t : 0.2f * t; h2[0][tid] = t * scl + sh;
        t = a1 + bs; t = (t >= 0.f) ? t : 0.2f * t; h2[1][tid] = t * scl + sh;
        t = a2 + bs; t = (t >= 0.f) ? t : 0.2f * t; h2[2][tid] = t * scl + sh;
        t = a3 + bs; t = (t >= 0.f) ? t : 0.2f * t; h2[3][tid] = t * scl + sh;
    }
    __syncthreads();
    if (tid < 32) {
        float am[4] = {0.f, 0.f, 0.f, 0.f}, al[4] = {0.f, 0.f, 0.f, 0.f};
        const float* wm = Wmu + tid * 64;
        const float* wl = Wlv + tid * 64;
        for (int k = 0; k < 64; k++) {
            float wmv = wm[k], wlv_ = wl[k];
#pragma unroll
            for (int it = 0; it < 4; it++) {
                am[it] += h2[it][k] * wmv;
                al[it] += h2[it][k] * wlv_;
            }
        }
        float bm = bmu[tid], bl = blv[tid];
#pragma unroll
        for (int it = 0; it < 4; it++) {
            float m = am[it] + bm;
            zz[it][tid] = m;
            mu_out[(b0 + it) * 32 + tid] = m;
            lv_out[(b0 + it) * 32 + tid] = al[it] + bl;
        }
    }
    __syncthreads();
    if (tid < 64) {
        float a[4] = {0.f, 0.f, 0.f, 0.f};
        const float* wr = D1 + tid * 32;
        for (int k = 0; k < 32; k++) {
            float wv = wr[k];
#pragma unroll
            for (int it = 0; it < 4; it++) a[it] += zz[it][k] * wv;
        }
        float bs = db1[tid], scl = dg1[tid] * BN_SC, sh = dbb1[tid];
#pragma unroll
        for (int it = 0; it < 4; it++) {
            float t = a[it] + bs; t = (t >= 0.f) ? t : 0.2f * t;
            d1[it][tid] = t * scl + sh;
        }
    }
    __syncthreads();
    {
        float a[4] = {0.f, 0.f, 0.f, 0.f};
        const float* wr = D2 + tid * 64;
        for (int k = 0; k < 64; k++) {
            float wv = wr[k];
#pragma unroll
            for (int it = 0; it < 4; it++) a[it] += d1[it][k] * wv;
        }
        float bs = db2[tid], scl = dg2[tid] * BN_SC, sh = dbb2[tid];
#pragma unroll
        for (int it = 0; it < 4; it++) {
            float t = a[it] + bs; t = (t >= 0.f) ? t : 0.2f * t;
            d2[it][tid] = t * scl + sh;
        }
    }
    __syncthreads();
    for (int j = tid; j < SPD; j += 128) {
        float a0 = 0.f, a1 = 0.f, a2 = 0.f, a3 = 0.f;
        const float* wr = D3 + (size_t)j * 128;
        for (int k = 0; k < 128; k++) {
            float wv = wr[k];
            a0 += d2[0][k] * wv; a1 += d2[1][k] * wv;
            a2 += d2[2][k] * wv; a3 += d2[3][k] * wv;
        }
        float bs = db3[j];
        vdec_out[(b0 + 0) * SPD + j] = a0 + bs;
        vdec_out[(b0 + 1) * SPD + j] = a1 + bs;
        vdec_out[(b0 + 2) * SPD + j] = a2 + bs;
        vdec_out[(b0 + 3) * SPD + j] = a3 + bs;
    }
}

extern "C" void kernel_launch(void* const* d_in, const int* in_sizes, int n_in,
                              void* d_out, int out_size)
{
    const float* x      = (const float*)d_in[0];
    const float* ref    = (const float*)d_in[1];
    const float* enc_w1 = (const float*)d_in[2];
    const float* enc_b1 = (const float*)d_in[3];
    const float* bn1_g  = (const float*)d_in[4];
    const float* bn1_b  = (const float*)d_in[5];
    const float* enc_w2 = (const float*)d_in[6];
    const float* enc_b2 = (const float*)d_in[7];
    const float* bn2_g  = (const float*)d_in[8];
    const float* bn2_b  = (const float*)d_in[9];
    const float* mu_w   = (const float*)d_in[10];
    const float* mu_b   = (const float*)d_in[11];
    const float* lv_w   = (const float*)d_in[12];
    const float* lv_b   = (const float*)d_in[13];
    const float* dec_w1 = (const float*)d_in[14];
    const float* dec_b1 = (const float*)d_in[15];
    const float* dbn1_g = (const float*)d_in[16];
    const float* dbn1_b = (const float*)d_in[17];
    const float* dec_w2 = (const float*)d_in[18];
    const float* dec_b2 = (const float*)d_in[19];
    const float* dbn2_g = (const float*)d_in[20];
    const float* dbn2_b = (const float*)d_in[21];
    const float* dec_w3 = (const float*)d_in[22];
    const float* dec_b3 = (const float*)d_in[23];

    float* out = (float*)d_out;

    float *p_rm, *p_rp, *p_vec, *p_mu, *p_lv, *p_vdec;
    cudaGetSymbolAddress((void**)&p_rm,   g_rm);
    cudaGetSymbolAddress((void**)&p_rp,   g_rp);
    cudaGetSymbolAddress((void**)&p_vec,  g_vec);
    cudaGetSymbolAddress((void**)&p_mu,   g_mu);
    cudaGetSymbolAddress((void**)&p_lv,   g_lv);
    cudaGetSymbolAddress((void**)&p_vdec, g_vdec);

    const long long need = (long long)NBATCH * 4096 + 2LL * NBATCH * 32;  // 17039360
    float* mu_dst = ((long long)out_size == need) ? out + (size_t)NBATCH * 4096 : p_mu;
    float* lv_dst = ((long long)out_size == need) ? out + (size_t)NBATCH * 4096 + (size_t)NBATCH * 32 : p_lv;

    prep_ref_kernel<<<1, 256, DYN_B>>>(ref, p_rm, p_rp);
    log_map_kernel<<<NBATCH, 256, DYN_B>>>(x, p_rm, p_rp, p_vec);

    mlp_fused_kernel<<<NBATCH / 4, 128>>>(p_vec,
        enc_w1, enc_b1, bn1_g, bn1_b,
        enc_w2, enc_b2, bn2_g, bn2_b,
        mu_w, mu_b, lv_w, lv_b,
        dec_w1, dec_b1, dbn1_g, dbn1_b,
        dec_w2, dec_b2, dbn2_g, dbn2_b,
        dec_w3, dec_b3,
        mu_dst, lv_dst, p_vdec);

    exp_map_kernel<<<NBATCH, 256, DYN_B>>>(ref, p_vdec, out);
}

// round 14
// speedup vs baseline: 1.6994x; 1.0733x over previous
#include <cuda_runtime.h>
#include <math.h>

#define NCH    64
#define PITCH  68
#define NBATCH 4096
#define SPD    2080
#define EPSV   1e-6f
#define BN_SC  0.9999950000375f
#define ROT_TOL 1e-6f

__device__ float g_rm[NCH * NCH];
__device__ float g_rp[NCH * NCH];
__device__ float g_vec [(size_t)NBATCH * SPD];
__device__ float g_mu  [(size_t)NBATCH * 32];
__device__ float g_lv  [(size_t)NBATCH * 32];
__device__ float g_vdec[(size_t)NBATCH * SPD];

__device__ __forceinline__ void iu_decode(int u, int& i, int& j)
{
    int lo = 0, hi = 63;
    while (lo < hi) {
        int mid = (lo + hi + 1) >> 1;
        if (((mid * (129 - mid)) >> 1) <= u) lo = mid; else hi = mid - 1;
    }
    i = lo;
    j = lo + (u - ((lo * (129 - lo)) >> 1));
}

// ---------------- in-block 64x64 GEMM, 4x4 tile/thread, scalar loads (low-reg) --------
// Compute into registers, BARRIER, then write — so dst may alias either operand.
template<int AP, int BP, bool BT, bool SC>
__device__ __forceinline__ void bgemm(const float* __restrict__ Ao,
                                      const float* __restrict__ Bo,
                                      const float* __restrict__ ksc,
                                      float* __restrict__ C, int tid)
{
    const int i0 = (tid >> 4) * 4, j0 = (tid & 15) * 4;
    float acc[4][4];
#pragma unroll
    for (int r = 0; r < 4; r++)
#pragma unroll
        for (int c = 0; c < 4; c++) acc[r][c] = 0.f;
    for (int k = 0; k < 64; k++) {
        float a[4], b[4];
#pragma unroll
        for (int r = 0; r < 4; r++) a[r] = Ao[(i0 + r) * AP + k];
        if (SC) {
            float f = ksc[k];
#pragma unroll
            for (int r = 0; r < 4; r++) a[r] *= f;
        }
#pragma unroll
        for (int c = 0; c < 4; c++)
            b[c] = BT ? Bo[(j0 + c) * BP + k] : Bo[k * BP + j0 + c];
#pragma unroll
        for (int r = 0; r < 4; r++)
#pragma unroll
            for (int c = 0; c < 4; c++) acc[r][c] += a[r] * b[c];
    }
    __syncthreads();
#pragma unroll
    for (int r = 0; r < 4; r++)
#pragma unroll
        for (int c = 0; c < 4; c++)
            C[(i0 + r) * PITCH + j0 + c] = acc[r][c];
    __syncthreads();
}

__device__ __forceinline__ void bgemm_vtv(const float* __restrict__ Vt,
                                          const float* __restrict__ d,
                                          float* __restrict__ C, int tid)
{
    const int i0 = (tid >> 4) * 4, j0 = (tid & 15) * 4;
    float acc[4][4];
#pragma unroll
    for (int r = 0; r < 4; r++)
#pragma unroll
        for (int c = 0; c < 4; c++) acc[r][c] = 0.f;
    for (int t = 0; t < 64; t++) {
        const float* row = Vt + t * PITCH;
        float dk = d[t];
        float a[4], b[4];
#pragma unroll
        for (int r = 0; r < 4; r++) a[r] = row[i0 + r] * dk;
#pragma unroll
        for (int c = 0; c < 4; c++) b[c] = row[j0 + c];
#pragma unroll
        for (int r = 0; r < 4; r++)
#pragma unroll
            for (int c = 0; c < 4; c++) acc[r][c] += a[r] * b[c];
    }
    __syncthreads();
#pragma unroll
    for (int r = 0; r < 4; r++)
#pragma unroll
        for (int c = 0; c < 4; c++)
            C[(i0 + r) * PITCH + j0 + c] = acc[r][c];
    __syncthreads();
}

// ---------------- one parallel-order Jacobi sweep (63 rounds), thresholded ----------------
// Rotations with |s| < ROT_TOL are snapped to identity; identity pairs skip their
// A-tile updates (per-lane) and V row-pair updates (warp-uniform).
template<bool WITHV>
__device__ __forceinline__ void jacobi_sweep(float* __restrict__ A, float* __restrict__ Vt,
                                             int lane, int warp)
{
    for (int r = 0; r < 63; r++) {
        int p, q;
        if (lane == 0) { p = 63; q = r; }
        else {
            p = lane + r;      if (p >= 63) p -= 63;
            q = 63 - lane + r; if (q >= 63) q -= 63;
        }
        float app = A[p * PITCH + p], aqq = A[q * PITCH + q];
        float apq = 0.5f * (A[p * PITCH + q] + A[q * PITCH + p]);
        float c = 1.f, s = 0.f;
        if (fabsf(apq) > 1e-36f) {
            float tau = (aqq - app) / (2.f * apq);
            float t = copysignf(1.f, tau) / (fabsf(tau) + sqrtf(1.f + tau * tau));
            c = rsqrtf(1.f + t * t);
            s = t * c;
            if (fabsf(s) < ROT_TOL) { c = 1.f; s = 0.f; }   // snap to identity
        }
        __syncthreads();
#pragma unroll
        for (int n = 0; n < 4; n++) {
            int a = warp + 8 * n;
            float ca = __shfl_sync(0xffffffffu, c, a);
            float sa = __shfl_sync(0xffffffffu, s, a);
            int   pa = __shfl_sync(0xffffffffu, p, a);
            int   qa = __shfl_sync(0xffffffffu, q, a);
            bool rowrot = (sa != 0.f);
            if (rowrot || (s != 0.f)) {
                float x00 = A[pa * PITCH + p], x01 = A[pa * PITCH + q];
                float x10 = A[qa * PITCH + p], x11 = A[qa * PITCH + q];
                float t00 = ca * x00 - sa * x10, t01 = ca * x01 - sa * x11;
                float t10 = sa * x00 + ca * x10, t11 = sa * x01 + ca * x11;
                A[pa * PITCH + p] = c * t00 - s * t01;
                A[pa * PITCH + q] = s * t00 + c * t01;
                A[qa * PITCH + p] = c * t10 - s * t11;
                A[qa * PITCH + q] = s * t10 + c * t11;
            }
            if (WITHV && rowrot) {   // warp-uniform branch
                float2* Pp = reinterpret_cast<float2*>(Vt + pa * PITCH) + lane;
                float2* Pq = reinterpret_cast<float2*>(Vt + qa * PITCH) + lane;
                float2 vp = *Pp, vq = *Pq;
                float2 np, nq;
                np.x = ca * vp.x - sa * vq.x; np.y = ca * vp.y - sa * vq.y;
                nq.x = sa * vp.x + ca * vq.x; nq.y = sa * vp.y + ca * vq.y;
                *Pp = np; *Pq = nq;
            }
        }
        __syncthreads();
    }
}

template<bool WITHV>
__device__ void jacobi64(float* __restrict__ A, float* __restrict__ Vt, int sweeps,
                         int lane, int warp)
{
    for (int sw = 0; sw < sweeps; sw++)
        jacobi_sweep<WITHV>(A, Vt, lane, warp);
}

// dynamic smem: A, Vt = 2 * 64*68 floats = 34816 B  -> 6 blocks/SM
#define DYN_B (2 * 64 * PITCH * (int)sizeof(float))

__global__ __launch_bounds__(256, 6)
void prep_ref_kernel(const float* __restrict__ ref,
                     float* __restrict__ rm_out, float* __restrict__ rp_out)
{
    extern __shared__ float smem[];
    float* A  = smem;
    float* Vt = smem + 64 * PITCH;
    __shared__ float w1[64], w2[64];
    int tid = threadIdx.x, lane = tid & 31, warp = tid >> 5;
    for (int idx = tid; idx < 4096; idx += 256) {
        int i = idx >> 6, j = idx & 63;
        A[i * PITCH + j] = ref[idx] + ((i == j) ? EPSV : 0.f);
        Vt[i * PITCH + j] = (i == j) ? 1.f : 0.f;
    }
    __syncthreads();
    jacobi64<true>(A, Vt, 12, lane, warp);
    if (tid < 64) {
        float w = fmaxf(A[tid * PITCH + tid], 1e-20f);
        w1[tid] = rsqrtf(w);
        w2[tid] = sqrtf(w);
    }
    __syncthreads();
    bgemm_vtv(Vt, w1, A, tid);
    for (int idx = tid; idx < 4096; idx += 256)
        rm_out[idx] = A[(idx >> 6) * PITCH + (idx & 63)];
    __syncthreads();
    bgemm_vtv(Vt, w2, A, tid);
    for (int idx = tid; idx < 4096; idx += 256)
        rp_out[idx] = A[(idx >> 6) * PITCH + (idx & 63)];
}

__global__ __launch_bounds__(256, 6)
void log_map_kernel(const float* __restrict__ x,
                    const float* __restrict__ rm, const float* __restrict__ rp,
                    float* __restrict__ vec_out)
{
    extern __shared__ float smem[];
    float* A  = smem;
    float* Vt = smem + 64 * PITCH;
    __shared__ float w[64];
    int tid = threadIdx.x, lane = tid & 31, warp = tid >> 5;
    const float* X = x + (size_t)blockIdx.x * 4096;
    for (int idx = tid; idx < 1024; idx += 256) {
        int i = idx >> 4, j4 = (idx & 15) << 2;
        *(float4*)(A + i * PITCH + j4) = *(const float4*)(X + i * 64 + j4);
    }
    __syncthreads();
    bgemm<64, PITCH, false, false>(rm, A, nullptr, Vt, tid);   // Vt = rm @ x
    bgemm<PITCH, 64, false, false>(Vt, rm, nullptr, A, tid);   // A = s = rm x rm
    for (int idx = tid; idx < 4096; idx += 256) {
        int i = idx >> 6, j = idx & 63;
        Vt[i * PITCH + j] = (i == j) ? 1.f : 0.f;
    }
    __syncthreads();
    jacobi64<true>(A, Vt, 7, lane, warp);
    if (tid < 64) w[tid] = logf(fmaxf(A[tid * PITCH + tid], 1e-12f));
    __syncthreads();
    bgemm_vtv(Vt, w, A, tid);                                  // A = log_s
    bgemm<64, PITCH, false, false>(rm, A, nullptr, A, tid);    // A = rm @ log_s
    bgemm<PITCH, 64, false, false>(A, rp, nullptr, A, tid);    // A = tang
    float* out = vec_out + (size_t)blockIdx.x * SPD;
    for (int u = tid; u < SPD; u += 256) {
        int i, j; iu_decode(u, i, j);
        out[u] = A[i * PITCH + j];
    }
}

__global__ __launch_bounds__(256, 6)
void exp_map_kernel(const float* __restrict__ ref,
                    const float* __restrict__ vdec_in,
                    float* __restrict__ recon)
{
    extern __shared__ float smem[];
    float* A  = smem;
    float* Vt = smem + 64 * PITCH;
    __shared__ float w[64];
    __shared__ float red[64];
    __shared__ float sh_shift;
    __shared__ int s_done;
    int tid = threadIdx.x, lane = tid & 31, warp = tid >> 5;
    const float* vd = vdec_in + (size_t)blockIdx.x * SPD;
    for (int u = tid; u < SPD; u += 256) {
        int i, j; iu_decode(u, i, j);
        float v = vd[u];
        if (i == j) A[i * PITCH + i] = v + EPSV;
        else { A[i * PITCH + j] = v; A[j * PITCH + i] = v; }
    }
    for (int idx = tid; idx < 4096; idx += 256) {
        int i = idx >> 6, j = idx & 63;
        Vt[i * PITCH + j] = (i == j) ? 1.f : 0.f;
    }
    __syncthreads();
    jacobi64<true>(A, Vt, 8, lane, warp);
    if (tid < 64) w[tid] = expf(A[tid * PITCH + tid]);
    __syncthreads();
    bgemm<64, PITCH, true, false>(ref, Vt, nullptr, A, tid);    // A = U = ref @ V
    bgemm<PITCH, PITCH, false, true>(A, Vt, w, A, tid);         // A = R = U diag(e^w) V^T
    for (int idx = tid; idx < 4096; idx += 256) {
        int i = idx >> 6, j = idx & 63;
        Vt[i * PITCH + j] = (i >= j) ? A[i * PITCH + j] : A[j * PITCH + i];
    }
    __syncthreads();
    float shf = 0.f;
    {
        int done = 0;
        for (int sw = 0; sw < 8 && !done; sw++) {
            jacobi_sweep<false>(Vt, nullptr, lane, warp);
            if (sw >= 2) {
                int row = tid >> 2, c0 = (tid & 3) << 4;
                float part = 0.f;
                for (int j = 0; j < 16; j++) {
                    int col = c0 + j;
                    float v = Vt[row * PITCH + col];
                    part += (col == row) ? 0.f : fabsf(v);
                }
                part += __shfl_down_sync(0xffffffffu, part, 2);
                part += __shfl_down_sync(0xffffffffu, part, 1);
                if ((tid & 3) == 0) red[row] = Vt[row * PITCH + row] - part;
                __syncthreads();
                if (tid == 0) {
                    float m = red[0];
                    for (int i = 1; i < 64; i++) m = fminf(m, red[i]);
                    s_done = (m > EPSV) ? 1 : 0;
                }
                __syncthreads();
                done = s_done;
                __syncthreads();
            }
        }
        if (!done) {
            if (tid == 0) {
                float m = Vt[0];
                for (int t = 1; t < 64; t++) m = fminf(m, Vt[t * PITCH + t]);
                sh_shift = fmaxf(EPSV - m, 0.f);
            }
            __syncthreads();
            shf = sh_shift;
        }
    }
    float* out = recon + (size_t)blockIdx.x * 4096;
    for (int idx = tid; idx < 1024; idx += 256) {
        int i = idx >> 4, j4 = (idx & 15) << 2;
        float4 v = *(const float4*)(A + i * PITCH + j4);
        if (i >= j4 && i < j4 + 4) ((float*)&v)[i - j4] += shf;
        *(float4*)(out + i * 64 + j4) = v;
    }
}

// ---------------- fused MLP: 4 items per 128-thread block (W reuse) ----------------
__global__ void mlp_fused_kernel(
    const float* __restrict__ vec,
    const float* __restrict__ W1, const float* __restrict__ b1,
    const float* __restrict__ g1, const float* __restrict__ bb1,
    const float* __restrict__ W2, const float* __restrict__ b2,
    const float* __restrict__ g2, const float* __restrict__ bb2,
    const float* __restrict__ Wmu, const float* __restrict__ bmu,
    const float* __restrict__ Wlv, const float* __restrict__ blv,
    const float* __restrict__ D1, const float* __restrict__ db1,
    const float* __restrict__ dg1, const float* __restrict__ dbb1,
    const float* __restrict__ D2, const float* __restrict__ db2,
    const float* __restrict__ dg2, const float* __restrict__ dbb2,
    const float* __restrict__ D3, const float* __restrict__ db3,
    float* __restrict__ mu_out, float* __restrict__ lv_out,
    float* __restrict__ vdec_out)
{
    __shared__ float sv[4][SPD];
    __shared__ float h1[4][128], h2[4][64], zz[4][32], d1[4][64], d2[4][128];
    const int tid = threadIdx.x;
    const size_t b0 = (size_t)blockIdx.x * 4;
#pragma unroll
    for (int it = 0; it < 4; it++)
        for (int u = tid; u < SPD; u += 128) sv[it][u] = vec[(b0 + it) * SPD + u];
    __syncthreads();
    {
        float a0 = 0.f, a1 = 0.f, a2 = 0.f, a3 = 0.f;
        const float* wr = W1 + (size_t)tid * SPD;
        for (int k = 0; k < SPD; k++) {
            float wv = wr[k];
            a0 += sv[0][k] * wv; a1 += sv[1][k] * wv;
            a2 += sv[2][k] * wv; a3 += sv[3][k] * wv;
        }
        float bs = b1[tid], scl = g1[tid] * BN_SC, sh = bb1[tid];
        float t;
        t = a0 + bs; t = (t >= 0.f) ? t : 0.2f * t; h1[0][tid] = t * scl + sh;
        t = a1 + bs; t = (t >= 0.f) ? t : 0.2f * t; h1[1][tid] = t * scl + sh;
        t = a2 + bs; t = (t >= 0.f) ? t : 0.2f * t; h1[2][tid] = t * scl + sh;
        t = a3 + bs; t = (t >= 0.f) ? t : 0.2f * t; h1[3][tid] = t * scl + sh;
    }
    __syncthreads();
    if (tid < 64) {
        float a0 = 0.f, a1 = 0.f, a2 = 0.f, a3 = 0.f;
        const float* wr = W2 + tid * 128;
        for (int k = 0; k < 128; k++) {
            float wv = wr[k];
            a0 += h1[0][k] * wv; a1 += h1[1][k] * wv;
            a2 += h1[2][k] * wv; a3 += h1[3][k] * wv;
        }
        float bs = b2[tid], scl = g2[tid] * BN_SC, sh = bb2[tid];
        float t;
        t = a0 + bs; t = (t >= 0.f) ? t : 0.2f * t; h2[0][tid] = t * scl + sh;
        t = a1 + bs; t = (t >= 0.f) ? t : 0.2f * t; h2[1][tid] = t * scl + sh;
        t = a2 + bs; t = (t >= 0.f) ? t : 0.2f * t; h2[2][tid] = t * scl + sh;
        t = a3 + bs; t = (t >= 0.f) ? t : 0.2f * t; h2[3][tid] = t * scl + sh;
    }
    __syncthreads();
    if (tid < 32) {
        float am[4] = {0.f, 0.f, 0.f, 0.f}, al[4] = {0.f, 0.f, 0.f, 0.f};
        const float* wm = Wmu + tid * 64;
        const float* wl = Wlv + tid * 64;
        for (int k = 0; k < 64; k++) {
            float wmv = wm[k], wlv_ = wl[k];
#pragma unroll
            for (int it = 0; it < 4; it++) {
                am[it] += h2[it][k] * wmv;
                al[it] += h2[it][k] * wlv_;
            }
        }
        float bm = bmu[tid], bl = blv[tid];
#pragma unroll
        for (int it = 0; it < 4; it++) {
            float m = am[it] + bm;
            zz[it][tid] = m;
            mu_out[(b0 + it) * 32 + tid] = m;
            lv_out[(b0 + it) * 32 + tid] = al[it] + bl;
        }
    }
    __syncthreads();
    if (tid < 64) {
        float a[4] = {0.f, 0.f, 0.f, 0.f};
        const float* wr = D1 + tid * 32;
        for (int k = 0; k < 32; k++) {
            float wv = wr[k];
#pragma unroll
            for (int it = 0; it < 4; it++) a[it] += zz[it][k] * wv;
        }
        float bs = db1[tid], scl = dg1[tid] * BN_SC, sh = dbb1[tid];
#pragma unroll
        for (int it = 0; it < 4; it++) {
            float t = a[it] + bs; t = (t >= 0.f) ? t : 0.2f * t;
            d1[it][tid] = t * scl + sh;
        }
    }
    __syncthreads();
    {
        float a[4] = {0.f, 0.f, 0.f, 0.f};
        const float* wr = D2 + tid * 64;
        for (int k = 0; k < 64; k++) {
            float wv = wr[k];
#pragma unroll
            for (int it = 0; it < 4; it++) a[it] += d1[it][k] * wv;
        }
        float bs = db2[tid], scl = dg2[tid] * BN_SC, sh = dbb2[tid];
#pragma unroll
        for (int it = 0; it < 4; it++) {
            float t = a[it] + bs; t = (t >= 0.f) ? t : 0.2f * t;
            d2[it][tid] = t * scl + sh;
        }
    }
    __syncthreads();
    for (int j = tid; j < SPD; j += 128) {
        float a0 = 0.f, a1 = 0.f, a2 = 0.f, a3 = 0.f;
        const float* wr = D3 + (size_t)j * 128;
        for (int k = 0; k < 128; k++) {
            float wv = wr[k];
            a0 += d2[0][k] * wv; a1 += d2[1][k] * wv;
            a2 += d2[2][k] * wv; a3 += d2[3][k] * wv;
        }
        float bs = db3[j];
        vdec_out[(b0 + 0) * SPD + j] = a0 + bs;
        vdec_out[(b0 + 1) * SPD + j] = a1 + bs;
        vdec_out[(b0 + 2) * SPD + j] = a2 + bs;
        vdec_out[(b0 + 3) * SPD + j] = a3 + bs;
    }
}

extern "C" void kernel_launch(void* const* d_in, const int* in_sizes, int n_in,
                              void* d_out, int out_size)
{
    const float* x      = (const float*)d_in[0];
    const float* ref    = (const float*)d_in[1];
    const float* enc_w1 = (const float*)d_in[2];
    const float* enc_b1 = (const float*)d_in[3];
    const float* bn1_g  = (const float*)d_in[4];
    const float* bn1_b  = (const float*)d_in[5];
    const float* enc_w2 = (const float*)d_in[6];
    const float* enc_b2 = (const float*)d_in[7];
    const float* bn2_g  = (const float*)d_in[8];
    const float* bn2_b  = (const float*)d_in[9];
    const float* mu_w   = (const float*)d_in[10];
    const float* mu_b   = (const float*)d_in[11];
    const float* lv_w   = (const float*)d_in[12];
    const float* lv_b   = (const float*)d_in[13];
    const float* dec_w1 = (const float*)d_in[14];
    const float* dec_b1 = (const float*)d_in[15];
    const float* dbn1_g = (const float*)d_in[16];
    const float* dbn1_b = (const float*)d_in[17];
    const float* dec_w2 = (const float*)d_in[18];
    const float* dec_b2 = (const float*)d_in[19];
    const float* dbn2_g = (const float*)d_in[20];
    const float* dbn2_b = (const float*)d_in[21];
    const float* dec_w3 = (const float*)d_in[22];
    const float* dec_b3 = (const float*)d_in[23];

    float* out = (float*)d_out;

    float *p_rm, *p_rp, *p_vec, *p_mu, *p_lv, *p_vdec;
    cudaGetSymbolAddress((void**)&p_rm,   g_rm);
    cudaGetSymbolAddress((void**)&p_rp,   g_rp);
    cudaGetSymbolAddress((void**)&p_vec,  g_vec);
    cudaGetSymbolAddress((void**)&p_mu,   g_mu);
    cudaGetSymbolAddress((void**)&p_lv,   g_lv);
    cudaGetSymbolAddress((void**)&p_vdec, g_vdec);

    const long long need = (long long)NBATCH * 4096 + 2LL * NBATCH * 32;  // 17039360
    float* mu_dst = ((long long)out_size == need) ? out + (size_t)NBATCH * 4096 : p_mu;
    float* lv_dst = ((long long)out_size == need) ? out + (size_t)NBATCH * 4096 + (size_t)NBATCH * 32 : p_lv;

    prep_ref_kernel<<<1, 256, DYN_B>>>(ref, p_rm, p_rp);
    log_map_kernel<<<NBATCH, 256, DYN_B>>>(x, p_rm, p_rp, p_vec);

    mlp_fused_kernel<<<NBATCH / 4, 128>>>(p_vec,
        enc_w1, enc_b1, bn1_g, bn1_b,
        enc_w2, enc_b2, bn2_g, bn2_b,
        mu_w, mu_b, lv_w, lv_b,
        dec_w1, dec_b1, dbn1_g, dbn1_b,
        dec_w2, dec_b2, dbn2_g, dbn2_b,
        dec_w3, dec_b3,
        mu_dst, lv_dst, p_vdec);

    exp_map_kernel<<<NBATCH, 256, DYN_B>>>(ref, p_vdec, out);
}